// round 1
// baseline (speedup 1.0000x reference)
#include <cuda_runtime.h>
#include <cuda_bf16.h>
#include <math.h>

#define N_NODES 50000
#define N_EDGES 1600000
#define D_IN    512
#define D_HEAD  64
#define H1      256   /* 4 heads * 64 */
#define D_OUT   64

typedef unsigned long long ull;

// ---------------- scratch (device globals; no allocation allowed) ----------
__device__ float g_t1[(size_t)N_NODES * H1];      // X @ W1cat      (51.2 MB)
__device__ float g_h [(size_t)N_NODES * H1];      // elu(agg1)      (51.2 MB)
__device__ float g_t2[(size_t)N_NODES * D_OUT];   // h @ W2         (12.8 MB)
__device__ float g_B1[D_IN * H1];                 // packed W1      (0.5 MB)
__device__ int   g_counts[N_NODES];
__device__ int   g_row_start[N_NODES + 1];
__device__ int   g_cursor[N_NODES];
__device__ int   g_sorted_dst[N_EDGES];

// ---------------- f32x2 helpers (Blackwell packed fp32 FMA, PTX-only) ------
__device__ __forceinline__ ull pk2(float x, float y) {
    ull r; asm("mov.b64 %0, {%1,%2};" : "=l"(r) : "f"(x), "f"(y)); return r;
}
__device__ __forceinline__ ull fma2(ull a, ull b, ull c) {
    ull d; asm("fma.rn.f32x2 %0, %1, %2, %3;" : "=l"(d) : "l"(a), "l"(b), "l"(c));
    return d;
}
__device__ __forceinline__ float2 upk(ull v) {
    float2 f; asm("mov.b64 {%0,%1}, %2;" : "=f"(f.x), "=f"(f.y) : "l"(v)); return f;
}
__device__ __forceinline__ float eluf(float x) { return x > 0.f ? x : expm1f(x); }

// ---------------- CSR build: histogram -> scan -> scatter -------------------
__global__ void zero_counts_kernel() {
    int i = blockIdx.x * blockDim.x + threadIdx.x;
    if (i < N_NODES) g_counts[i] = 0;
}

__global__ void hist_kernel(const int* __restrict__ ei) {
    int e = blockIdx.x * blockDim.x + threadIdx.x;
    if (e < N_EDGES) atomicAdd(&g_counts[ei[e]], 1);
}

// Single-block multi-tile exclusive scan over 50000 counts.
__global__ void scan_kernel() {
    __shared__ int sh[1024];
    __shared__ int carry_sh;
    int tid = threadIdx.x;
    if (tid == 0) carry_sh = 0;
    __syncthreads();
    for (int base = 0; base < N_NODES; base += 1024) {
        int v = (base + tid < N_NODES) ? g_counts[base + tid] : 0;
        sh[tid] = v;
        __syncthreads();
        #pragma unroll
        for (int ofs = 1; ofs < 1024; ofs <<= 1) {
            int t = (tid >= ofs) ? sh[tid - ofs] : 0;
            __syncthreads();
            sh[tid] += t;
            __syncthreads();
        }
        int incl = sh[tid];
        int c = carry_sh;
        if (base + tid < N_NODES) {
            g_row_start[base + tid] = c + incl - v;
            g_cursor[base + tid]    = c + incl - v;
        }
        __syncthreads();
        if (tid == 1023) carry_sh = c + sh[1023];
        __syncthreads();
    }
    if (tid == 0) g_row_start[N_NODES] = carry_sh;
}

__global__ void scatter_kernel(const int* __restrict__ ei) {
    int e = blockIdx.x * blockDim.x + threadIdx.x;
    if (e < N_EDGES) {
        int s = ei[e];
        int d = ei[N_EDGES + e];
        int pos = atomicAdd(&g_cursor[s], 1);
        g_sorted_dst[pos] = d;
    }
}

// Pack W1 (4,512,64) -> B1 (512,256) so layer-1 is one GEMM.
__global__ void pack_b1_kernel(const float* __restrict__ W1) {
    int idx = blockIdx.x * blockDim.x + threadIdx.x;
    if (idx < D_IN * H1) {
        int k = idx >> 8;
        int c = idx & 255;
        int i = c >> 6, j = c & 63;
        g_B1[idx] = W1[i * (D_IN * D_HEAD) + k * D_HEAD + j];
    }
}

// ---------------- fp32 GEMM (f32x2 packed FMA, 256 threads, TMxTN tiles) ----
template <int BM, int BN, int BK, int TM, int TN>
__global__ void __launch_bounds__(256)
gemm_kernel(const float* __restrict__ A, const float* __restrict__ B,
            float* __restrict__ C, int M, int N, int K) {
    __shared__ float As[BK * BM];   // k-major: As[k*BM + m]
    __shared__ float Bs[BK * BN];   // Bs[k*BN + n]
    const int tid = threadIdx.x;
    const int tx = tid & 15;        // BN/TN == 16
    const int ty = tid >> 4;        // BM/TM == 16
    const int m0 = blockIdx.y * BM;
    const int n0 = blockIdx.x * BN;

    constexpr int A_V4 = BM * BK / 4 / 256;
    constexpr int B_V4 = BN * BK / 4 / 256;
    float4 pa[A_V4], pb[B_V4];

    auto loadG = [&](int kt) {
        #pragma unroll
        for (int r = 0; r < A_V4; r++) {
            int idx = (tid + r * 256) * 4;
            int arow = idx / BK, acol = idx % BK;
            int gm = m0 + arow;
            if (gm < M) pa[r] = *(const float4*)&A[(size_t)gm * K + kt + acol];
            else        pa[r] = make_float4(0.f, 0.f, 0.f, 0.f);
        }
        #pragma unroll
        for (int r = 0; r < B_V4; r++) {
            int idx = (tid + r * 256) * 4;
            int brow = idx / BN, bcol = idx % BN;
            pb[r] = *(const float4*)&B[(size_t)(kt + brow) * N + n0 + bcol];
        }
    };
    auto storeS = [&]() {
        #pragma unroll
        for (int r = 0; r < A_V4; r++) {
            int idx = (tid + r * 256) * 4;
            int arow = idx / BK, acol = idx % BK;
            As[(acol + 0) * BM + arow] = pa[r].x;
            As[(acol + 1) * BM + arow] = pa[r].y;
            As[(acol + 2) * BM + arow] = pa[r].z;
            As[(acol + 3) * BM + arow] = pa[r].w;
        }
        #pragma unroll
        for (int r = 0; r < B_V4; r++) {
            int idx = (tid + r * 256) * 4;
            *(float4*)&Bs[idx] = pb[r];
        }
    };

    ull acc[TM][TN / 2];
    #pragma unroll
    for (int i = 0; i < TM; i++)
        #pragma unroll
        for (int j = 0; j < TN / 2; j++) acc[i][j] = 0ull;

    loadG(0); storeS(); __syncthreads();

    for (int kt = 0; kt < K; kt += BK) {
        bool more = (kt + BK) < K;
        if (more) loadG(kt + BK);
        #pragma unroll
        for (int k = 0; k < BK; k++) {
            float ar[TM];
            #pragma unroll
            for (int s = 0; s < TM / 4; s++) {
                float4 a4 = *(const float4*)&As[k * BM + s * 64 + ty * 4];
                ar[s * 4 + 0] = a4.x; ar[s * 4 + 1] = a4.y;
                ar[s * 4 + 2] = a4.z; ar[s * 4 + 3] = a4.w;
            }
            ull b2[TN / 2];
            #pragma unroll
            for (int s = 0; s < TN / 4; s++) {
                float4 b4 = *(const float4*)&Bs[k * BN + s * 64 + tx * 4];
                b2[s * 2 + 0] = pk2(b4.x, b4.y);
                b2[s * 2 + 1] = pk2(b4.z, b4.w);
            }
            #pragma unroll
            for (int i = 0; i < TM; i++) {
                ull ad = pk2(ar[i], ar[i]);
                #pragma unroll
                for (int j = 0; j < TN / 2; j++)
                    acc[i][j] = fma2(ad, b2[j], acc[i][j]);
            }
        }
        __syncthreads();
        if (more) { storeS(); __syncthreads(); }
    }

    #pragma unroll
    for (int i = 0; i < TM; i++) {
        int row = m0 + (i / 4) * 64 + ty * 4 + (i % 4);
        if (row < M) {
            #pragma unroll
            for (int j = 0; j < TN / 2; j++) {
                int col = n0 + (j / 2) * 64 + tx * 4 + (j % 2) * 2;
                float2 v = upk(acc[i][j]);
                *(float2*)&C[(size_t)row * N + col] = v;
            }
        }
    }
}

// ---------------- layer-1 aggregate + ELU (warp per node, 256 feats) --------
__global__ void __launch_bounds__(256) agg1_kernel() {
    int gw = (blockIdx.x * 256 + threadIdx.x) >> 5;
    int lane = threadIdx.x & 31;
    if (gw >= N_NODES) return;
    int beg = g_row_start[gw], end = g_row_start[gw + 1];

    float4 a0 = make_float4(0.f, 0.f, 0.f, 0.f);
    float4 a1 = make_float4(0.f, 0.f, 0.f, 0.f);
    for (int eb = beg; eb < end; eb += 32) {
        int n = min(32, end - eb);
        int myd = (lane < n) ? g_sorted_dst[eb + lane] : 0;
        for (int i = 0; i < n; i++) {
            int d = __shfl_sync(0xffffffffu, myd, i);
            const float4* p = (const float4*)(g_t1 + (size_t)d * H1);
            float4 v0 = p[lane];
            float4 v1 = p[lane + 32];
            a0.x += v0.x; a0.y += v0.y; a0.z += v0.z; a0.w += v0.w;
            a1.x += v1.x; a1.y += v1.y; a1.z += v1.z; a1.w += v1.w;
        }
    }
    float inv = (end > beg) ? 1.f / (float)(end - beg) : 0.f;
    float4 o0, o1;
    o0.x = eluf(a0.x * inv); o0.y = eluf(a0.y * inv);
    o0.z = eluf(a0.z * inv); o0.w = eluf(a0.w * inv);
    o1.x = eluf(a1.x * inv); o1.y = eluf(a1.y * inv);
    o1.z = eluf(a1.z * inv); o1.w = eluf(a1.w * inv);
    float4* hp = (float4*)(g_h + (size_t)gw * H1);
    hp[lane]      = o0;
    hp[lane + 32] = o1;
}

// ---------------- layer-2 aggregate (warp per node, 64 feats) ---------------
__global__ void __launch_bounds__(256) agg2_kernel(float* __restrict__ out) {
    int gw = (blockIdx.x * 256 + threadIdx.x) >> 5;
    int lane = threadIdx.x & 31;
    if (gw >= N_NODES) return;
    int beg = g_row_start[gw], end = g_row_start[gw + 1];

    float ax = 0.f, ay = 0.f;
    for (int eb = beg; eb < end; eb += 32) {
        int n = min(32, end - eb);
        int myd = (lane < n) ? g_sorted_dst[eb + lane] : 0;
        for (int i = 0; i < n; i++) {
            int d = __shfl_sync(0xffffffffu, myd, i);
            const float2* p = (const float2*)(g_t2 + (size_t)d * D_OUT);
            float2 v = p[lane];
            ax += v.x; ay += v.y;
        }
    }
    float inv = (end > beg) ? 1.f / (float)(end - beg) : 0.f;
    float2 o; o.x = ax * inv; o.y = ay * inv;
    ((float2*)(out + (size_t)gw * D_OUT))[lane] = o;
}

// ---------------- launch ----------------------------------------------------
extern "C" void kernel_launch(void* const* d_in, const int* in_sizes, int n_in,
                              void* d_out, int out_size) {
    const float* X  = (const float*)d_in[0];
    const int*   ei = (const int*)d_in[1];
    const float* W1 = (const float*)d_in[2];
    const float* W2 = (const float*)d_in[3];
    float* out = (float*)d_out;

    void* p;
    cudaGetSymbolAddress(&p, g_t1); float* t1 = (float*)p;
    cudaGetSymbolAddress(&p, g_h);  float* h  = (float*)p;
    cudaGetSymbolAddress(&p, g_t2); float* t2 = (float*)p;
    cudaGetSymbolAddress(&p, g_B1); float* B1 = (float*)p;

    zero_counts_kernel<<<(N_NODES + 255) / 256, 256>>>();
    hist_kernel<<<(N_EDGES + 255) / 256, 256>>>(ei);
    scan_kernel<<<1, 1024>>>();
    scatter_kernel<<<(N_EDGES + 255) / 256, 256>>>(ei);
    pack_b1_kernel<<<(D_IN * H1 + 255) / 256, 256>>>(W1);

    dim3 g1(H1 / 128, (N_NODES + 127) / 128);
    gemm_kernel<128, 128, 8, 8, 8><<<g1, 256>>>(X, B1, t1, N_NODES, H1, D_IN);

    agg1_kernel<<<(N_NODES * 32 + 255) / 256, 256>>>();

    dim3 g2(D_OUT / 64, (N_NODES + 127) / 128);
    gemm_kernel<128, 64, 16, 8, 4><<<g2, 256>>>(h, W2, t2, N_NODES, D_OUT, H1);

    agg2_kernel<<<(N_NODES * 32 + 255) / 256, 256>>>(out);
}

// round 3
// speedup vs baseline: 1.4133x; 1.4133x over previous
#include <cuda_runtime.h>
#include <cuda_bf16.h>
#include <math.h>
#include <stdint.h>

#define N_NODES 50000
#define N_EDGES 1600000
#define D_IN    512
#define D_HEAD  64
#define H1      256   /* 4 heads * 64 */
#define D_OUT   64

typedef unsigned long long ull;

// ---------------- scratch (device globals; no allocation allowed) ----------
__device__ float g_t1[(size_t)N_NODES * H1];            // X @ W1cat (fp32)
__device__ float g_t2[(size_t)N_NODES * D_OUT];         // h @ W2
__device__ __nv_bfloat16 g_Xhi[(size_t)N_NODES * D_IN];
__device__ __nv_bfloat16 g_Xlo[(size_t)N_NODES * D_IN];
__device__ __nv_bfloat16 g_Hhi[(size_t)N_NODES * H1];   // elu(agg1) hi/lo
__device__ __nv_bfloat16 g_Hlo[(size_t)N_NODES * H1];
__device__ __nv_bfloat16 g_B1hi[H1 * D_IN];             // W1 packed [N=256][K=512]
__device__ __nv_bfloat16 g_B1lo[H1 * D_IN];
__device__ __nv_bfloat16 g_B2hi[D_OUT * H1];            // W2 packed [N=64][K=256]
__device__ __nv_bfloat16 g_B2lo[D_OUT * H1];
__device__ int   g_counts[N_NODES];
__device__ int   g_row_start[N_NODES + 1];
__device__ int   g_cursor[N_NODES];
__device__ int   g_sorted_dst[N_EDGES];
__device__ int   g_bsums[64];
__device__ int   g_boff[64];

// ---------------- helpers ---------------------------------------------------
__device__ __forceinline__ float eluf(float x) { return x > 0.f ? x : expm1f(x); }
__device__ __forceinline__ uint32_t smem_u32(const void* p) {
    uint32_t a;
    asm("{ .reg .u64 t; cvta.to.shared.u64 t, %1; cvt.u32.u64 %0, t; }" : "=r"(a) : "l"(p));
    return a;
}
__device__ __forceinline__ void ldsm4(uint32_t& r0, uint32_t& r1, uint32_t& r2, uint32_t& r3,
                                      uint32_t addr) {
    asm volatile("ldmatrix.sync.aligned.m8n8.x4.shared.b16 {%0,%1,%2,%3}, [%4];"
                 : "=r"(r0), "=r"(r1), "=r"(r2), "=r"(r3) : "r"(addr));
}
__device__ __forceinline__ void mma16816(float* c, uint32_t a0, uint32_t a1, uint32_t a2,
                                         uint32_t a3, uint32_t b0, uint32_t b1) {
    asm volatile(
        "mma.sync.aligned.m16n8k16.row.col.f32.bf16.bf16.f32 "
        "{%0,%1,%2,%3}, {%4,%5,%6,%7}, {%8,%9}, {%0,%1,%2,%3};"
        : "+f"(c[0]), "+f"(c[1]), "+f"(c[2]), "+f"(c[3])
        : "r"(a0), "r"(a1), "r"(a2), "r"(a3), "r"(b0), "r"(b1));
}

// ---------------- CSR build: histogram -> 3-phase scan -> scatter -----------
__global__ void zero_counts_kernel() {
    int i = blockIdx.x * blockDim.x + threadIdx.x;
    if (i < N_NODES) g_counts[i] = 0;
}
__global__ void hist_kernel(const int* __restrict__ ei) {
    int e = blockIdx.x * blockDim.x + threadIdx.x;
    if (e < N_EDGES) atomicAdd(&g_counts[ei[e]], 1);
}
#define SCAN_NB 49   /* ceil(50000/1024) */
__global__ void __launch_bounds__(1024) scan1_kernel() {
    __shared__ int wsum[32];
    int tid = threadIdx.x, lane = tid & 31, wid = tid >> 5;
    int i = blockIdx.x * 1024 + tid;
    int v = (i < N_NODES) ? g_counts[i] : 0;
    int x = v;
    #pragma unroll
    for (int o = 1; o < 32; o <<= 1) {
        int t = __shfl_up_sync(0xffffffffu, x, o);
        if (lane >= o) x += t;
    }
    if (lane == 31) wsum[wid] = x;
    __syncthreads();
    if (wid == 0) {
        int s = wsum[lane];
        #pragma unroll
        for (int o = 1; o < 32; o <<= 1) {
            int t = __shfl_up_sync(0xffffffffu, s, o);
            if (lane >= o) s += t;
        }
        wsum[lane] = s;
    }
    __syncthreads();
    int boff = (wid > 0) ? wsum[wid - 1] : 0;
    int incl = x + boff;
    if (i < N_NODES) g_row_start[i] = incl - v;
    if (tid == 1023) g_bsums[blockIdx.x] = incl;
}
__global__ void scan2_kernel() {
    __shared__ int sh[64];
    int t = threadIdx.x;
    int v = (t < SCAN_NB) ? g_bsums[t] : 0;
    sh[t] = v;
    __syncthreads();
    #pragma unroll
    for (int o = 1; o < 64; o <<= 1) {
        int val = (t >= o) ? sh[t - o] : 0;
        __syncthreads();
        sh[t] += val;
        __syncthreads();
    }
    if (t < SCAN_NB) g_boff[t] = sh[t] - v;
}
__global__ void __launch_bounds__(1024) scan3_kernel() {
    int i = blockIdx.x * 1024 + threadIdx.x;
    if (i < N_NODES) {
        int rs = g_row_start[i] + g_boff[blockIdx.x];
        g_row_start[i] = rs;
        g_cursor[i] = rs;
    }
    if (i == 0) g_row_start[N_NODES] = N_EDGES;
}
__global__ void scatter_kernel(const int* __restrict__ ei) {
    int e = blockIdx.x * blockDim.x + threadIdx.x;
    if (e < N_EDGES) {
        int s = ei[e];
        int d = ei[N_EDGES + e];
        int pos = atomicAdd(&g_cursor[s], 1);
        g_sorted_dst[pos] = d;
    }
}

// ---------------- bf16 hi/lo conversions ------------------------------------
__global__ void conv_x_kernel(const float* __restrict__ X) {
    int idx = blockIdx.x * blockDim.x + threadIdx.x;    // one float4 per thread
    if (idx >= N_NODES * D_IN / 4) return;
    float4 v = ((const float4*)X)[idx];
    float a[4] = {v.x, v.y, v.z, v.w};
    __nv_bfloat16 hi[4], lo[4];
    #pragma unroll
    for (int j = 0; j < 4; j++) {
        hi[j] = __float2bfloat16_rn(a[j]);
        lo[j] = __float2bfloat16_rn(a[j] - __bfloat162float(hi[j]));
    }
    __nv_bfloat162* ph = (__nv_bfloat162*)g_Xhi;
    __nv_bfloat162* pl = (__nv_bfloat162*)g_Xlo;
    ph[idx * 2 + 0] = __nv_bfloat162(hi[0], hi[1]);
    ph[idx * 2 + 1] = __nv_bfloat162(hi[2], hi[3]);
    pl[idx * 2 + 0] = __nv_bfloat162(lo[0], lo[1]);
    pl[idx * 2 + 1] = __nv_bfloat162(lo[2], lo[3]);
}
// pack W1 (4,512,64) -> [N=256][K=512] K-contiguous, bf16 hi/lo
__global__ void pack_b1_kernel(const float* __restrict__ W1) {
    int idx = blockIdx.x * blockDim.x + threadIdx.x;
    if (idx >= H1 * D_IN) return;
    int n = idx >> 9, k = idx & 511;
    int head = n >> 6, j = n & 63;
    float w = W1[head * (D_IN * D_HEAD) + k * D_HEAD + j];
    __nv_bfloat16 hi = __float2bfloat16_rn(w);
    g_B1hi[idx] = hi;
    g_B1lo[idx] = __float2bfloat16_rn(w - __bfloat162float(hi));
}
// pack W2 (256,64) -> [N=64][K=256] K-contiguous, bf16 hi/lo
__global__ void pack_b2_kernel(const float* __restrict__ W2) {
    int idx = blockIdx.x * blockDim.x + threadIdx.x;
    if (idx >= D_OUT * H1) return;
    int n = idx >> 8, k = idx & 255;
    float w = W2[k * D_OUT + n];
    __nv_bfloat16 hi = __float2bfloat16_rn(w);
    g_B2hi[idx] = hi;
    g_B2lo[idx] = __float2bfloat16_rn(w - __bfloat162float(hi));
}

// ---------------- HMMA GEMM: C[M,N] = A[M,K] @ B[N,K]^T --------------------
// bf16 hi/lo 3-term split, fp32 accumulate via mma.sync.m16n8k16.
// BK=32; smem rows padded to 40 bf16 (80B) -> ldmatrix conflict-free.
#define BKC 32
#define RS  40   /* padded row stride in bf16 */

template <int BM, int BN, int WARPS_M, int WARPS_N>
__global__ void __launch_bounds__(WARPS_M * WARPS_N * 32)
gemm_mma_kernel(const __nv_bfloat16* __restrict__ Ahi, const __nv_bfloat16* __restrict__ Alo,
                const __nv_bfloat16* __restrict__ Bhi, const __nv_bfloat16* __restrict__ Blo,
                float* __restrict__ C, int M, int N, int K) {
    constexpr int NT = WARPS_M * WARPS_N * 32;
    constexpr int WM = BM / WARPS_M;       // 32
    constexpr int WN = BN / WARPS_N;       // 32
    constexpr int TM = WM / 16;            // 2
    constexpr int TN2 = WN / 16;           // ldsm x4 pairs along N
    constexpr int TN = WN / 8;             // 4

    __shared__ __nv_bfloat16 sAh[BM * RS], sAl[BM * RS];
    __shared__ __nv_bfloat16 sBh[BN * RS], sBl[BN * RS];

    const int tid = threadIdx.x;
    const int wid = tid >> 5, lane = tid & 31;
    const int wm0 = (wid / WARPS_N) * WM;
    const int wn0 = (wid % WARPS_N) * WN;
    const int m0 = blockIdx.y * BM;
    const int n0 = blockIdx.x * BN;

    const uint32_t aHb = smem_u32(sAh), aLb = smem_u32(sAl);
    const uint32_t bHb = smem_u32(sBh), bLb = smem_u32(sBl);

    float acc[TM][TN][4];
    #pragma unroll
    for (int i = 0; i < TM; i++)
        #pragma unroll
        for (int j = 0; j < TN; j++)
            #pragma unroll
            for (int q = 0; q < 4; q++) acc[i][j][q] = 0.f;

    const uint4 z4 = make_uint4(0, 0, 0, 0);
    const int ldRow = lane & 15;
    const int ldCol = (lane >> 4) * 8;

    for (int kt = 0; kt < K; kt += BKC) {
        // load A tile (BM x 32) hi+lo
        #pragma unroll
        for (int i = tid; i < BM * 4; i += NT) {
            int row = i >> 2, seg = i & 3;
            bool ok = (m0 + row) < M;
            size_t src = ((size_t)(m0 + row) * K + kt + seg * 8) >> 3;
            uint32_t so = (uint32_t)(row * RS + seg * 8);
            *(uint4*)&sAh[so] = ok ? ((const uint4*)Ahi)[src] : z4;
            *(uint4*)&sAl[so] = ok ? ((const uint4*)Alo)[src] : z4;
        }
        // load B tile (BN x 32) hi+lo
        #pragma unroll
        for (int i = tid; i < BN * 4; i += NT) {
            int row = i >> 2, seg = i & 3;
            size_t src = ((size_t)(n0 + row) * K + kt + seg * 8) >> 3;
            uint32_t so = (uint32_t)(row * RS + seg * 8);
            *(uint4*)&sBh[so] = ((const uint4*)Bhi)[src];
            *(uint4*)&sBl[so] = ((const uint4*)Blo)[src];
        }
        __syncthreads();

        #pragma unroll
        for (int s = 0; s < 2; s++) {              // two k16 steps
            const int kb = s * 16;
            uint32_t ah[TM][4], al[TM][4];
            #pragma unroll
            for (int t = 0; t < TM; t++) {
                uint32_t off = (uint32_t)((wm0 + t * 16 + ldRow) * RS + kb + ldCol) * 2;
                ldsm4(ah[t][0], ah[t][1], ah[t][2], ah[t][3], aHb + off);
                ldsm4(al[t][0], al[t][1], al[t][2], al[t][3], aLb + off);
            }
            uint32_t bh[TN2][4], bl[TN2][4];
            #pragma unroll
            for (int t = 0; t < TN2; t++) {
                uint32_t off = (uint32_t)((wn0 + t * 16 + ldRow) * RS + kb + ldCol) * 2;
                ldsm4(bh[t][0], bh[t][1], bh[t][2], bh[t][3], bHb + off);
                ldsm4(bl[t][0], bl[t][1], bl[t][2], bl[t][3], bLb + off);
            }
            #pragma unroll
            for (int i = 0; i < TM; i++) {
                #pragma unroll
                for (int j = 0; j < TN; j++) {
                    int t2 = j >> 1, odd = j & 1;
                    uint32_t b0h = bh[t2][odd], b1h = bh[t2][odd + 2];
                    uint32_t b0l = bl[t2][odd], b1l = bl[t2][odd + 2];
                    mma16816(acc[i][j], ah[i][0], ah[i][1], ah[i][2], ah[i][3], b0h, b1h);
                    mma16816(acc[i][j], ah[i][0], ah[i][1], ah[i][2], ah[i][3], b0l, b1l);
                    mma16816(acc[i][j], al[i][0], al[i][1], al[i][2], al[i][3], b0h, b1h);
                }
            }
        }
        __syncthreads();
    }

    // epilogue: c0,c1 -> (row, col..col+1); c2,c3 -> (row+8, ...)
    #pragma unroll
    for (int i = 0; i < TM; i++) {
        int r0 = m0 + wm0 + i * 16 + (lane >> 2);
        #pragma unroll
        for (int j = 0; j < TN; j++) {
            int col = n0 + wn0 + j * 8 + (lane & 3) * 2;
            if (r0 < M) {
                float2 v = make_float2(acc[i][j][0], acc[i][j][1]);
                *(float2*)&C[(size_t)r0 * N + col] = v;
            }
            if (r0 + 8 < M) {
                float2 v = make_float2(acc[i][j][2], acc[i][j][3]);
                *(float2*)&C[(size_t)(r0 + 8) * N + col] = v;
            }
        }
    }
}

// ---------------- layer-1 aggregate + ELU -> bf16 hi/lo ---------------------
__global__ void __launch_bounds__(256) agg1_kernel() {
    int gw = (blockIdx.x * 256 + threadIdx.x) >> 5;
    int lane = threadIdx.x & 31;
    if (gw >= N_NODES) return;
    int beg = g_row_start[gw], end = g_row_start[gw + 1];

    float4 a0 = make_float4(0.f, 0.f, 0.f, 0.f);
    float4 a1 = make_float4(0.f, 0.f, 0.f, 0.f);
    for (int eb = beg; eb < end; eb += 32) {
        int n = min(32, end - eb);
        int myd = (lane < n) ? g_sorted_dst[eb + lane] : 0;
        for (int i = 0; i < n; i++) {
            int d = __shfl_sync(0xffffffffu, myd, i);
            const float4* p = (const float4*)(g_t1 + (size_t)d * H1);
            float4 v0 = p[lane];
            float4 v1 = p[lane + 32];
            a0.x += v0.x; a0.y += v0.y; a0.z += v0.z; a0.w += v0.w;
            a1.x += v1.x; a1.y += v1.y; a1.z += v1.z; a1.w += v1.w;
        }
    }
    float inv = (end > beg) ? 1.f / (float)(end - beg) : 0.f;
    float o[8];
    o[0] = eluf(a0.x * inv); o[1] = eluf(a0.y * inv);
    o[2] = eluf(a0.z * inv); o[3] = eluf(a0.w * inv);
    o[4] = eluf(a1.x * inv); o[5] = eluf(a1.y * inv);
    o[6] = eluf(a1.z * inv); o[7] = eluf(a1.w * inv);

    __nv_bfloat162* ph = (__nv_bfloat162*)(g_Hhi + (size_t)gw * H1);
    __nv_bfloat162* pl = (__nv_bfloat162*)(g_Hlo + (size_t)gw * H1);
    #pragma unroll
    for (int half = 0; half < 2; half++) {
        __nv_bfloat16 hi0 = __float2bfloat16_rn(o[half * 4 + 0]);
        __nv_bfloat16 hi1 = __float2bfloat16_rn(o[half * 4 + 1]);
        __nv_bfloat16 hi2 = __float2bfloat16_rn(o[half * 4 + 2]);
        __nv_bfloat16 hi3 = __float2bfloat16_rn(o[half * 4 + 3]);
        __nv_bfloat16 lo0 = __float2bfloat16_rn(o[half * 4 + 0] - __bfloat162float(hi0));
        __nv_bfloat16 lo1 = __float2bfloat16_rn(o[half * 4 + 1] - __bfloat162float(hi1));
        __nv_bfloat16 lo2 = __float2bfloat16_rn(o[half * 4 + 2] - __bfloat162float(hi2));
        __nv_bfloat16 lo3 = __float2bfloat16_rn(o[half * 4 + 3] - __bfloat162float(hi3));
        int base = half * 64 + lane * 2;   // bf162 index: cols half*128 + lane*4
        ph[base + 0] = __nv_bfloat162(hi0, hi1);
        ph[base + 1] = __nv_bfloat162(hi2, hi3);
        pl[base + 0] = __nv_bfloat162(lo0, lo1);
        pl[base + 1] = __nv_bfloat162(lo2, lo3);
    }
}

// ---------------- layer-2 aggregate (warp per node, 64 feats) ---------------
__global__ void __launch_bounds__(256) agg2_kernel(float* __restrict__ out) {
    int gw = (blockIdx.x * 256 + threadIdx.x) >> 5;
    int lane = threadIdx.x & 31;
    if (gw >= N_NODES) return;
    int beg = g_row_start[gw], end = g_row_start[gw + 1];

    float ax = 0.f, ay = 0.f;
    for (int eb = beg; eb < end; eb += 32) {
        int n = min(32, end - eb);
        int myd = (lane < n) ? g_sorted_dst[eb + lane] : 0;
        for (int i = 0; i < n; i++) {
            int d = __shfl_sync(0xffffffffu, myd, i);
            const float2* p = (const float2*)(g_t2 + (size_t)d * D_OUT);
            float2 v = p[lane];
            ax += v.x; ay += v.y;
        }
    }
    float inv = (end > beg) ? 1.f / (float)(end - beg) : 0.f;
    float2 o; o.x = ax * inv; o.y = ay * inv;
    ((float2*)(out + (size_t)gw * D_OUT))[lane] = o;
}

// ---------------- launch ----------------------------------------------------
extern "C" void kernel_launch(void* const* d_in, const int* in_sizes, int n_in,
                              void* d_out, int out_size) {
    const float* X  = (const float*)d_in[0];
    const int*   ei = (const int*)d_in[1];
    const float* W1 = (const float*)d_in[2];
    const float* W2 = (const float*)d_in[3];
    float* out = (float*)d_out;

    void* p;
    cudaGetSymbolAddress(&p, g_t1);   float* t1 = (float*)p;
    cudaGetSymbolAddress(&p, g_t2);   float* t2 = (float*)p;
    cudaGetSymbolAddress(&p, g_Xhi);  __nv_bfloat16* Xhi = (__nv_bfloat16*)p;
    cudaGetSymbolAddress(&p, g_Xlo);  __nv_bfloat16* Xlo = (__nv_bfloat16*)p;
    cudaGetSymbolAddress(&p, g_Hhi);  __nv_bfloat16* Hhi = (__nv_bfloat16*)p;
    cudaGetSymbolAddress(&p, g_Hlo);  __nv_bfloat16* Hlo = (__nv_bfloat16*)p;
    cudaGetSymbolAddress(&p, g_B1hi); __nv_bfloat16* B1hi = (__nv_bfloat16*)p;
    cudaGetSymbolAddress(&p, g_B1lo); __nv_bfloat16* B1lo = (__nv_bfloat16*)p;
    cudaGetSymbolAddress(&p, g_B2hi); __nv_bfloat16* B2hi = (__nv_bfloat16*)p;
    cudaGetSymbolAddress(&p, g_B2lo); __nv_bfloat16* B2lo = (__nv_bfloat16*)p;

    // CSR build
    zero_counts_kernel<<<(N_NODES + 255) / 256, 256>>>();
    hist_kernel<<<(N_EDGES + 255) / 256, 256>>>(ei);
    scan1_kernel<<<SCAN_NB, 1024>>>();
    scan2_kernel<<<1, 64>>>();
    scan3_kernel<<<SCAN_NB, 1024>>>();
    scatter_kernel<<<(N_EDGES + 255) / 256, 256>>>(ei);

    // bf16 hi/lo conversions
    conv_x_kernel<<<(N_NODES * D_IN / 4 + 255) / 256, 256>>>(X);
    pack_b1_kernel<<<(H1 * D_IN + 255) / 256, 256>>>(W1);
    pack_b2_kernel<<<(D_OUT * H1 + 255) / 256, 256>>>(W2);

    // Layer 1 GEMM (HMMA): t1 = X @ B1^T   [50000,512] x [256,512]
    {
        dim3 grid(H1 / 128, (N_NODES + 127) / 128);
        gemm_mma_kernel<128, 128, 4, 4><<<grid, 512>>>(Xhi, Xlo, B1hi, B1lo,
                                                       t1, N_NODES, H1, D_IN);
    }

    agg1_kernel<<<(N_NODES * 32 + 255) / 256, 256>>>();

    // Layer 2 GEMM (HMMA): t2 = h @ B2^T   [50000,256] x [64,256]
    {
        dim3 grid(1, (N_NODES + 127) / 128);
        gemm_mma_kernel<128, 64, 4, 2><<<grid, 256>>>(Hhi, Hlo, B2hi, B2lo,
                                                      t2, N_NODES, D_OUT, H1);
    }

    agg2_kernel<<<(N_NODES * 32 + 255) / 256, 256>>>(out);
}

// round 4
// speedup vs baseline: 1.4616x; 1.0342x over previous
#include <cuda_runtime.h>
#include <cuda_bf16.h>
#include <cuda_fp16.h>
#include <math.h>
#include <stdint.h>

#define N_NODES 50000
#define N_EDGES 1600000
#define D_IN    512
#define D_HEAD  64
#define H1      256   /* 4 heads * 64 */
#define D_OUT   64

// ---------------- scratch (device globals; no allocation allowed) ----------
__device__ __half g_t1h[(size_t)N_NODES * H1];          // X @ W1cat (fp16)
__device__ float  g_t2[(size_t)N_NODES * D_OUT];        // h @ W2 (fp32)
__device__ __nv_bfloat16 g_Xhi[(size_t)N_NODES * D_IN];
__device__ __nv_bfloat16 g_Xlo[(size_t)N_NODES * D_IN];
__device__ __nv_bfloat16 g_Hhi[(size_t)N_NODES * H1];   // elu(agg1) hi/lo
__device__ __nv_bfloat16 g_Hlo[(size_t)N_NODES * H1];
__device__ __nv_bfloat16 g_B1hi[H1 * D_IN];             // W1 packed [N=256][K=512]
__device__ __nv_bfloat16 g_B1lo[H1 * D_IN];
__device__ __nv_bfloat16 g_B2hi[D_OUT * H1];            // W2 packed [N=64][K=256]
__device__ __nv_bfloat16 g_B2lo[D_OUT * H1];
__device__ int   g_counts[N_NODES];
__device__ int   g_row_start[N_NODES + 1];
__device__ int   g_cursor[N_NODES];
__device__ int   g_sorted_dst[N_EDGES];
__device__ int   g_bsums[64];
__device__ int   g_boff[64];

// ---------------- helpers ---------------------------------------------------
__device__ __forceinline__ float eluf(float x) { return x > 0.f ? x : expm1f(x); }
__device__ __forceinline__ uint32_t smem_u32(const void* p) {
    uint32_t a;
    asm("{ .reg .u64 t; cvta.to.shared.u64 t, %1; cvt.u32.u64 %0, t; }" : "=r"(a) : "l"(p));
    return a;
}
__device__ __forceinline__ void ldsm4(uint32_t& r0, uint32_t& r1, uint32_t& r2, uint32_t& r3,
                                      uint32_t addr) {
    asm volatile("ldmatrix.sync.aligned.m8n8.x4.shared.b16 {%0,%1,%2,%3}, [%4];"
                 : "=r"(r0), "=r"(r1), "=r"(r2), "=r"(r3) : "r"(addr));
}
__device__ __forceinline__ void mma16816(float* c, uint32_t a0, uint32_t a1, uint32_t a2,
                                         uint32_t a3, uint32_t b0, uint32_t b1) {
    asm volatile(
        "mma.sync.aligned.m16n8k16.row.col.f32.bf16.bf16.f32 "
        "{%0,%1,%2,%3}, {%4,%5,%6,%7}, {%8,%9}, {%0,%1,%2,%3};"
        : "+f"(c[0]), "+f"(c[1]), "+f"(c[2]), "+f"(c[3])
        : "r"(a0), "r"(a1), "r"(a2), "r"(a3), "r"(b0), "r"(b1));
}
__device__ __forceinline__ void cpa16(uint32_t saddr, const void* gaddr, int sz) {
    asm volatile("cp.async.cg.shared.global [%0], [%1], 16, %2;"
                 :: "r"(saddr), "l"(gaddr), "r"(sz));
}
#define CPA_COMMIT() asm volatile("cp.async.commit_group;" ::: "memory")

__device__ __forceinline__ void store_pair(float* C, size_t off, float x, float y) {
    *(float2*)(C + off) = make_float2(x, y);
}
__device__ __forceinline__ void store_pair(__half* C, size_t off, float x, float y) {
    *(__half2*)(C + off) = __floats2half2_rn(x, y);
}

// ---------------- CSR build: histogram -> 3-phase scan -> scatter -----------
__global__ void zero_counts_kernel() {
    int i = blockIdx.x * blockDim.x + threadIdx.x;
    if (i < N_NODES) g_counts[i] = 0;
}
__global__ void hist_kernel(const int* __restrict__ ei) {
    int e = blockIdx.x * blockDim.x + threadIdx.x;
    if (e < N_EDGES) atomicAdd(&g_counts[ei[e]], 1);
}
#define SCAN_NB 49   /* ceil(50000/1024) */
__global__ void __launch_bounds__(1024) scan1_kernel() {
    __shared__ int wsum[32];
    int tid = threadIdx.x, lane = tid & 31, wid = tid >> 5;
    int i = blockIdx.x * 1024 + tid;
    int v = (i < N_NODES) ? g_counts[i] : 0;
    int x = v;
    #pragma unroll
    for (int o = 1; o < 32; o <<= 1) {
        int t = __shfl_up_sync(0xffffffffu, x, o);
        if (lane >= o) x += t;
    }
    if (lane == 31) wsum[wid] = x;
    __syncthreads();
    if (wid == 0) {
        int s = wsum[lane];
        #pragma unroll
        for (int o = 1; o < 32; o <<= 1) {
            int t = __shfl_up_sync(0xffffffffu, s, o);
            if (lane >= o) s += t;
        }
        wsum[lane] = s;
    }
    __syncthreads();
    int boff = (wid > 0) ? wsum[wid - 1] : 0;
    int incl = x + boff;
    if (i < N_NODES) g_row_start[i] = incl - v;
    if (tid == 1023) g_bsums[blockIdx.x] = incl;
}
__global__ void scan2_kernel() {
    __shared__ int sh[64];
    int t = threadIdx.x;
    int v = (t < SCAN_NB) ? g_bsums[t] : 0;
    sh[t] = v;
    __syncthreads();
    #pragma unroll
    for (int o = 1; o < 64; o <<= 1) {
        int val = (t >= o) ? sh[t - o] : 0;
        __syncthreads();
        sh[t] += val;
        __syncthreads();
    }
    if (t < SCAN_NB) g_boff[t] = sh[t] - v;
}
__global__ void __launch_bounds__(1024) scan3_kernel() {
    int i = blockIdx.x * 1024 + threadIdx.x;
    if (i < N_NODES) {
        int rs = g_row_start[i] + g_boff[blockIdx.x];
        g_row_start[i] = rs;
        g_cursor[i] = rs;
    }
    if (i == 0) g_row_start[N_NODES] = N_EDGES;
}
__global__ void scatter_kernel(const int* __restrict__ ei) {
    int e = blockIdx.x * blockDim.x + threadIdx.x;
    if (e < N_EDGES) {
        int s = ei[e];
        int d = ei[N_EDGES + e];
        int pos = atomicAdd(&g_cursor[s], 1);
        g_sorted_dst[pos] = d;
    }
}

// ---------------- bf16 hi/lo conversions ------------------------------------
__global__ void conv_x_kernel(const float* __restrict__ X) {
    int idx = blockIdx.x * blockDim.x + threadIdx.x;    // one float4 per thread
    if (idx >= N_NODES * D_IN / 4) return;
    float4 v = ((const float4*)X)[idx];
    float a[4] = {v.x, v.y, v.z, v.w};
    __nv_bfloat16 hi[4], lo[4];
    #pragma unroll
    for (int j = 0; j < 4; j++) {
        hi[j] = __float2bfloat16_rn(a[j]);
        lo[j] = __float2bfloat16_rn(a[j] - __bfloat162float(hi[j]));
    }
    __nv_bfloat162* ph = (__nv_bfloat162*)g_Xhi;
    __nv_bfloat162* pl = (__nv_bfloat162*)g_Xlo;
    ph[idx * 2 + 0] = __nv_bfloat162(hi[0], hi[1]);
    ph[idx * 2 + 1] = __nv_bfloat162(hi[2], hi[3]);
    pl[idx * 2 + 0] = __nv_bfloat162(lo[0], lo[1]);
    pl[idx * 2 + 1] = __nv_bfloat162(lo[2], lo[3]);
}
__global__ void pack_b1_kernel(const float* __restrict__ W1) {
    int idx = blockIdx.x * blockDim.x + threadIdx.x;
    if (idx >= H1 * D_IN) return;
    int n = idx >> 9, k = idx & 511;
    int head = n >> 6, j = n & 63;
    float w = W1[head * (D_IN * D_HEAD) + k * D_HEAD + j];
    __nv_bfloat16 hi = __float2bfloat16_rn(w);
    g_B1hi[idx] = hi;
    g_B1lo[idx] = __float2bfloat16_rn(w - __bfloat162float(hi));
}
__global__ void pack_b2_kernel(const float* __restrict__ W2) {
    int idx = blockIdx.x * blockDim.x + threadIdx.x;
    if (idx >= D_OUT * H1) return;
    int n = idx >> 8, k = idx & 255;
    float w = W2[k * D_OUT + n];
    __nv_bfloat16 hi = __float2bfloat16_rn(w);
    g_B2hi[idx] = hi;
    g_B2lo[idx] = __float2bfloat16_rn(w - __bfloat162float(hi));
}

// ---------------- HMMA GEMM (cp.async 2-stage pipeline) ---------------------
// C[M,N] = A[M,K] @ B[N,K]^T ; bf16 hi/lo 3-term split, fp32 accum.
#define BKC 32
#define RS  40   /* padded row stride in bf16 */

template <int BM, int BN, int WARPS_M, int WARPS_N, typename OutT>
__global__ void __launch_bounds__(WARPS_M * WARPS_N * 32)
gemm_mma_kernel(const __nv_bfloat16* __restrict__ Ahi, const __nv_bfloat16* __restrict__ Alo,
                const __nv_bfloat16* __restrict__ Bhi, const __nv_bfloat16* __restrict__ Blo,
                OutT* __restrict__ C, int M, int N, int K) {
    constexpr int NT = WARPS_M * WARPS_N * 32;
    constexpr int WM = BM / WARPS_M;
    constexpr int WN = BN / WARPS_N;
    constexpr int TM = WM / 16;
    constexpr int TN2 = WN / 16;
    constexpr int TN = WN / 8;
    constexpr int SA = BM * RS;                // elems
    constexpr int SB = BN * RS;
    constexpr int STAGE = 2 * SA + 2 * SB;     // elems per stage

    extern __shared__ __nv_bfloat16 sm[];
    const uint32_t smb = smem_u32(sm);

    const int tid = threadIdx.x;
    const int wid = tid >> 5, lane = tid & 31;
    const int wm0 = (wid / WARPS_N) * WM;
    const int wn0 = (wid % WARPS_N) * WN;
    const int m0 = blockIdx.y * BM;
    const int n0 = blockIdx.x * BN;
    const int NC = K / BKC;

    float acc[TM][TN][4];
    #pragma unroll
    for (int i = 0; i < TM; i++)
        #pragma unroll
        for (int j = 0; j < TN; j++)
            #pragma unroll
            for (int q = 0; q < 4; q++) acc[i][j][q] = 0.f;

    auto issue = [&](int c) {
        int st = c & 1;
        int kt = c * BKC;
        uint32_t aH = smb + (uint32_t)(st * STAGE) * 2;
        uint32_t aL = aH + SA * 2;
        uint32_t bH = aL + SA * 2;
        uint32_t bL = bH + SB * 2;
        #pragma unroll
        for (int i = tid; i < BM * 4; i += NT) {
            int row = i >> 2, seg = i & 3;
            int gm = m0 + row;
            int sz = (gm < M) ? 16 : 0;
            int gmc = gm < M ? gm : (M - 1);
            size_t gsrc = (size_t)gmc * K + kt + seg * 8;
            uint32_t so = (uint32_t)(row * RS + seg * 8) * 2;
            cpa16(aH + so, Ahi + gsrc, sz);
            cpa16(aL + so, Alo + gsrc, sz);
        }
        #pragma unroll
        for (int i = tid; i < BN * 4; i += NT) {
            int row = i >> 2, seg = i & 3;
            size_t gsrc = (size_t)(n0 + row) * K + kt + seg * 8;
            uint32_t so = (uint32_t)(row * RS + seg * 8) * 2;
            cpa16(bH + so, Bhi + gsrc, 16);
            cpa16(bL + so, Blo + gsrc, 16);
        }
        CPA_COMMIT();
    };

    const int ldRow = lane & 15;
    const int ldCol = (lane >> 4) * 8;

    issue(0);
    for (int c = 0; c < NC; c++) {
        bool more = (c + 1) < NC;
        if (more) issue(c + 1);
        if (more) asm volatile("cp.async.wait_group 1;" ::: "memory");
        else      asm volatile("cp.async.wait_group 0;" ::: "memory");
        __syncthreads();

        int st = c & 1;
        uint32_t aH = smb + (uint32_t)(st * STAGE) * 2;
        uint32_t aL = aH + SA * 2;
        uint32_t bH = aL + SA * 2;
        uint32_t bL = bH + SB * 2;

        #pragma unroll
        for (int s = 0; s < 2; s++) {
            const int kb = s * 16;
            uint32_t ah[TM][4], al[TM][4];
            #pragma unroll
            for (int t = 0; t < TM; t++) {
                uint32_t off = (uint32_t)((wm0 + t * 16 + ldRow) * RS + kb + ldCol) * 2;
                ldsm4(ah[t][0], ah[t][1], ah[t][2], ah[t][3], aH + off);
                ldsm4(al[t][0], al[t][1], al[t][2], al[t][3], aL + off);
            }
            uint32_t bh[TN2][4], bl[TN2][4];
            #pragma unroll
            for (int t = 0; t < TN2; t++) {
                uint32_t off = (uint32_t)((wn0 + t * 16 + ldRow) * RS + kb + ldCol) * 2;
                ldsm4(bh[t][0], bh[t][1], bh[t][2], bh[t][3], bH + off);
                ldsm4(bl[t][0], bl[t][1], bl[t][2], bl[t][3], bL + off);
            }
            #pragma unroll
            for (int i = 0; i < TM; i++) {
                #pragma unroll
                for (int j = 0; j < TN; j++) {
                    int t2 = j >> 1, odd = j & 1;
                    uint32_t b0h = bh[t2][odd], b1h = bh[t2][odd + 2];
                    uint32_t b0l = bl[t2][odd], b1l = bl[t2][odd + 2];
                    mma16816(acc[i][j], ah[i][0], ah[i][1], ah[i][2], ah[i][3], b0h, b1h);
                    mma16816(acc[i][j], ah[i][0], ah[i][1], ah[i][2], ah[i][3], b0l, b1l);
                    mma16816(acc[i][j], al[i][0], al[i][1], al[i][2], al[i][3], b0h, b1h);
                }
            }
        }
        __syncthreads();
    }

    #pragma unroll
    for (int i = 0; i < TM; i++) {
        int r0 = m0 + wm0 + i * 16 + (lane >> 2);
        #pragma unroll
        for (int j = 0; j < TN; j++) {
            int col = n0 + wn0 + j * 8 + (lane & 3) * 2;
            if (r0 < M)
                store_pair(C, (size_t)r0 * N + col, acc[i][j][0], acc[i][j][1]);
            if (r0 + 8 < M)
                store_pair(C, (size_t)(r0 + 8) * N + col, acc[i][j][2], acc[i][j][3]);
        }
    }
}

// ---------------- layer-1 aggregate + ELU -> bf16 hi/lo ---------------------
// block per node, 128 threads, thread handles 2 features (half2 loads).
__global__ void __launch_bounds__(128) agg1_kernel() {
    int node = blockIdx.x;
    int tid = threadIdx.x;
    int beg = g_row_start[node], end = g_row_start[node + 1];
    __shared__ int sd[128];

    const __half2* t1h = (const __half2*)g_t1h;   // row = 128 half2
    float ax = 0.f, ay = 0.f;

    for (int base = beg; base < end; base += 128) {
        int n = min(128, end - base);
        if (tid < n) sd[tid] = g_sorted_dst[base + tid];
        __syncthreads();
        int e = 0;
        for (; e + 4 <= n; e += 4) {
            int d0 = sd[e], d1 = sd[e + 1], d2 = sd[e + 2], d3 = sd[e + 3];
            float2 f0 = __half22float2(t1h[(size_t)d0 * 128 + tid]);
            float2 f1 = __half22float2(t1h[(size_t)d1 * 128 + tid]);
            float2 f2 = __half22float2(t1h[(size_t)d2 * 128 + tid]);
            float2 f3 = __half22float2(t1h[(size_t)d3 * 128 + tid]);
            ax += f0.x + f1.x + f2.x + f3.x;
            ay += f0.y + f1.y + f2.y + f3.y;
        }
        for (; e < n; e++) {
            float2 f = __half22float2(t1h[(size_t)sd[e] * 128 + tid]);
            ax += f.x; ay += f.y;
        }
        __syncthreads();
    }
    int deg = end - beg;
    float inv = deg > 0 ? 1.f / (float)deg : 0.f;
    float o0 = eluf(ax * inv), o1 = eluf(ay * inv);
    __nv_bfloat16 h0 = __float2bfloat16_rn(o0);
    __nv_bfloat16 h1 = __float2bfloat16_rn(o1);
    __nv_bfloat16 l0 = __float2bfloat16_rn(o0 - __bfloat162float(h0));
    __nv_bfloat16 l1 = __float2bfloat16_rn(o1 - __bfloat162float(h1));
    ((__nv_bfloat162*)g_Hhi)[(size_t)node * 128 + tid] = __nv_bfloat162(h0, h1);
    ((__nv_bfloat162*)g_Hlo)[(size_t)node * 128 + tid] = __nv_bfloat162(l0, l1);
}

// ---------------- layer-2 aggregate (block per node, 64 threads) ------------
__global__ void __launch_bounds__(64) agg2_kernel(float* __restrict__ out) {
    int node = blockIdx.x;
    int tid = threadIdx.x;
    int beg = g_row_start[node], end = g_row_start[node + 1];
    __shared__ int sd[64];

    float a = 0.f;
    for (int base = beg; base < end; base += 64) {
        int n = min(64, end - base);
        if (tid < n) sd[tid] = g_sorted_dst[base + tid];
        __syncthreads();
        int e = 0;
        for (; e + 4 <= n; e += 4) {
            int d0 = sd[e], d1 = sd[e + 1], d2 = sd[e + 2], d3 = sd[e + 3];
            float v0 = g_t2[(size_t)d0 * D_OUT + tid];
            float v1 = g_t2[(size_t)d1 * D_OUT + tid];
            float v2 = g_t2[(size_t)d2 * D_OUT + tid];
            float v3 = g_t2[(size_t)d3 * D_OUT + tid];
            a += v0 + v1 + v2 + v3;
        }
        for (; e < n; e++) a += g_t2[(size_t)sd[e] * D_OUT + tid];
        __syncthreads();
    }
    int deg = end - beg;
    float inv = deg > 0 ? 1.f / (float)deg : 0.f;
    out[(size_t)node * D_OUT + tid] = a * inv;
}

// ---------------- launch ----------------------------------------------------
extern "C" void kernel_launch(void* const* d_in, const int* in_sizes, int n_in,
                              void* d_out, int out_size) {
    const float* X  = (const float*)d_in[0];
    const int*   ei = (const int*)d_in[1];
    const float* W1 = (const float*)d_in[2];
    const float* W2 = (const float*)d_in[3];
    float* out = (float*)d_out;

    void* p;
    cudaGetSymbolAddress(&p, g_t1h);  __half* t1 = (__half*)p;
    cudaGetSymbolAddress(&p, g_t2);   float* t2 = (float*)p;
    cudaGetSymbolAddress(&p, g_Xhi);  __nv_bfloat16* Xhi = (__nv_bfloat16*)p;
    cudaGetSymbolAddress(&p, g_Xlo);  __nv_bfloat16* Xlo = (__nv_bfloat16*)p;
    cudaGetSymbolAddress(&p, g_Hhi);  __nv_bfloat16* Hhi = (__nv_bfloat16*)p;
    cudaGetSymbolAddress(&p, g_Hlo);  __nv_bfloat16* Hlo = (__nv_bfloat16*)p;
    cudaGetSymbolAddress(&p, g_B1hi); __nv_bfloat16* B1hi = (__nv_bfloat16*)p;
    cudaGetSymbolAddress(&p, g_B1lo); __nv_bfloat16* B1lo = (__nv_bfloat16*)p;
    cudaGetSymbolAddress(&p, g_B2hi); __nv_bfloat16* B2hi = (__nv_bfloat16*)p;
    cudaGetSymbolAddress(&p, g_B2lo); __nv_bfloat16* B2lo = (__nv_bfloat16*)p;

    // smem budgets (bytes): stage = (2*BM*RS + 2*BN*RS)*2 ; 2 stages
    const int SMEM1 = 2 * (2 * 128 * RS + 2 * 128 * RS) * 2;   // 81920
    const int SMEM2 = 2 * (2 * 128 * RS + 2 * 64 * RS) * 2;    // 61440
    cudaFuncSetAttribute((const void*)gemm_mma_kernel<128, 128, 4, 4, __half>,
                         cudaFuncAttributeMaxDynamicSharedMemorySize, SMEM1);
    cudaFuncSetAttribute((const void*)gemm_mma_kernel<128, 64, 4, 2, float>,
                         cudaFuncAttributeMaxDynamicSharedMemorySize, SMEM2);

    // --- conversions first so gemm1 lands in the ncu profiling slot (#4) ---
    conv_x_kernel<<<(N_NODES * D_IN / 4 + 255) / 256, 256>>>(X);
    pack_b1_kernel<<<(H1 * D_IN + 255) / 256, 256>>>(W1);
    pack_b2_kernel<<<(D_OUT * H1 + 255) / 256, 256>>>(W2);

    // Layer 1 GEMM (HMMA, pipelined): t1h = X @ B1^T
    {
        dim3 grid(H1 / 128, (N_NODES + 127) / 128);
        gemm_mma_kernel<128, 128, 4, 4, __half><<<grid, 512, SMEM1>>>(
            Xhi, Xlo, B1hi, B1lo, t1, N_NODES, H1, D_IN);
    }

    // CSR build
    zero_counts_kernel<<<(N_NODES + 255) / 256, 256>>>();
    hist_kernel<<<(N_EDGES + 255) / 256, 256>>>(ei);
    scan1_kernel<<<SCAN_NB, 1024>>>();
    scan2_kernel<<<1, 64>>>();
    scan3_kernel<<<SCAN_NB, 1024>>>();
    scatter_kernel<<<(N_EDGES + 255) / 256, 256>>>(ei);

    agg1_kernel<<<N_NODES, 128>>>();

    // Layer 2 GEMM (HMMA, pipelined): t2 = h @ B2^T
    {
        dim3 grid(1, (N_NODES + 127) / 128);
        gemm_mma_kernel<128, 64, 4, 2, float><<<grid, 256, SMEM2>>>(
            Hhi, Hlo, B2hi, B2lo, t2, N_NODES, D_OUT, H1);
    }

    agg2_kernel<<<N_NODES, 64>>>(out);
}

// round 5
// speedup vs baseline: 1.7676x; 1.2093x over previous
#include <cuda_runtime.h>
#include <cuda_bf16.h>
#include <cuda_fp16.h>
#include <math.h>
#include <stdint.h>

#define N_NODES 50000
#define N_EDGES 1600000
#define D_IN    512
#define D_HEAD  64
#define H1      256   /* 4 heads * 64 */
#define D_OUT   64

// ---------------- scratch (device globals; no allocation allowed) ----------
__device__ __half g_t1h[(size_t)N_NODES * H1];          // X @ W1cat (fp16)
__device__ float  g_t2[(size_t)N_NODES * D_OUT];        // h @ W2 (fp32)
__device__ __half g_Xhi[(size_t)N_NODES * D_IN];        // fp16 hi/lo split of X
__device__ __half g_Xlo[(size_t)N_NODES * D_IN];
__device__ __half g_Hhi[(size_t)N_NODES * H1];          // elu(agg1) hi/lo fp16
__device__ __half g_Hlo[(size_t)N_NODES * H1];
__device__ __half g_B1[H1 * D_IN];                      // W1 packed [N=256][K=512] fp16
__device__ __half g_B2[D_OUT * H1];                     // W2 packed [N=64][K=256] fp16
__device__ int   g_counts[N_NODES];
__device__ int   g_row_start[N_NODES + 1];
__device__ int   g_cursor[N_NODES];
__device__ int   g_sorted_dst[N_EDGES];
__device__ int   g_bsums[64];
__device__ int   g_boff[64];

// ---------------- helpers ---------------------------------------------------
__device__ __forceinline__ float eluf(float x) { return x > 0.f ? x : expm1f(x); }
__device__ __forceinline__ uint32_t smem_u32(const void* p) {
    uint32_t a;
    asm("{ .reg .u64 t; cvta.to.shared.u64 t, %1; cvt.u32.u64 %0, t; }" : "=r"(a) : "l"(p));
    return a;
}
__device__ __forceinline__ void ldsm4(uint32_t& r0, uint32_t& r1, uint32_t& r2, uint32_t& r3,
                                      uint32_t addr) {
    asm volatile("ldmatrix.sync.aligned.m8n8.x4.shared.b16 {%0,%1,%2,%3}, [%4];"
                 : "=r"(r0), "=r"(r1), "=r"(r2), "=r"(r3) : "r"(addr));
}
__device__ __forceinline__ void mma16816h(float* c, uint32_t a0, uint32_t a1, uint32_t a2,
                                          uint32_t a3, uint32_t b0, uint32_t b1) {
    asm volatile(
        "mma.sync.aligned.m16n8k16.row.col.f32.f16.f16.f32 "
        "{%0,%1,%2,%3}, {%4,%5,%6,%7}, {%8,%9}, {%0,%1,%2,%3};"
        : "+f"(c[0]), "+f"(c[1]), "+f"(c[2]), "+f"(c[3])
        : "r"(a0), "r"(a1), "r"(a2), "r"(a3), "r"(b0), "r"(b1));
}
__device__ __forceinline__ void cpa16(uint32_t saddr, const void* gaddr, int sz) {
    asm volatile("cp.async.cg.shared.global [%0], [%1], 16, %2;"
                 :: "r"(saddr), "l"(gaddr), "r"(sz));
}
#define CPA_COMMIT() asm volatile("cp.async.commit_group;" ::: "memory")

__device__ __forceinline__ void store_pair(float* C, size_t off, float x, float y) {
    *(float2*)(C + off) = make_float2(x, y);
}
__device__ __forceinline__ void store_pair(__half* C, size_t off, float x, float y) {
    *(__half2*)(C + off) = __floats2half2_rn(x, y);
}

// ---------------- CSR build: histogram -> 3-phase scan -> scatter -----------
__global__ void zero_counts_kernel() {
    int i = blockIdx.x * blockDim.x + threadIdx.x;
    if (i < N_NODES) g_counts[i] = 0;
}
__global__ void hist_kernel(const int* __restrict__ ei) {
    int e = blockIdx.x * blockDim.x + threadIdx.x;
    if (e < N_EDGES) atomicAdd(&g_counts[ei[e]], 1);
}
#define SCAN_NB 49   /* ceil(50000/1024) */
__global__ void __launch_bounds__(1024) scan1_kernel() {
    __shared__ int wsum[32];
    int tid = threadIdx.x, lane = tid & 31, wid = tid >> 5;
    int i = blockIdx.x * 1024 + tid;
    int v = (i < N_NODES) ? g_counts[i] : 0;
    int x = v;
    #pragma unroll
    for (int o = 1; o < 32; o <<= 1) {
        int t = __shfl_up_sync(0xffffffffu, x, o);
        if (lane >= o) x += t;
    }
    if (lane == 31) wsum[wid] = x;
    __syncthreads();
    if (wid == 0) {
        int s = wsum[lane];
        #pragma unroll
        for (int o = 1; o < 32; o <<= 1) {
            int t = __shfl_up_sync(0xffffffffu, s, o);
            if (lane >= o) s += t;
        }
        wsum[lane] = s;
    }
    __syncthreads();
    int boff = (wid > 0) ? wsum[wid - 1] : 0;
    int incl = x + boff;
    if (i < N_NODES) g_row_start[i] = incl - v;
    if (tid == 1023) g_bsums[blockIdx.x] = incl;
}
__global__ void scan2_kernel() {
    __shared__ int sh[64];
    int t = threadIdx.x;
    int v = (t < SCAN_NB) ? g_bsums[t] : 0;
    sh[t] = v;
    __syncthreads();
    #pragma unroll
    for (int o = 1; o < 64; o <<= 1) {
        int val = (t >= o) ? sh[t - o] : 0;
        __syncthreads();
        sh[t] += val;
        __syncthreads();
    }
    if (t < SCAN_NB) g_boff[t] = sh[t] - v;
}
__global__ void __launch_bounds__(1024) scan3_kernel() {
    int i = blockIdx.x * 1024 + threadIdx.x;
    if (i < N_NODES) {
        int rs = g_row_start[i] + g_boff[blockIdx.x];
        g_row_start[i] = rs;
        g_cursor[i] = rs;
    }
    if (i == 0) g_row_start[N_NODES] = N_EDGES;
}
__global__ void scatter_kernel(const int* __restrict__ ei) {
    int e = blockIdx.x * blockDim.x + threadIdx.x;
    if (e < N_EDGES) {
        int s = ei[e];
        int d = ei[N_EDGES + e];
        int pos = atomicAdd(&g_cursor[s], 1);
        g_sorted_dst[pos] = d;
    }
}

// ---------------- fp16 hi/lo conversions ------------------------------------
__global__ void conv_x_kernel(const float* __restrict__ X) {
    int idx = blockIdx.x * blockDim.x + threadIdx.x;    // one float4 per thread
    if (idx >= N_NODES * D_IN / 4) return;
    float4 v = ((const float4*)X)[idx];
    float a[4] = {v.x, v.y, v.z, v.w};
    __half hi[4], lo[4];
    #pragma unroll
    for (int j = 0; j < 4; j++) {
        hi[j] = __float2half_rn(a[j]);
        lo[j] = __float2half_rn(a[j] - __half2float(hi[j]));
    }
    __half2* ph = (__half2*)g_Xhi;
    __half2* pl = (__half2*)g_Xlo;
    ph[idx * 2 + 0] = __halves2half2(hi[0], hi[1]);
    ph[idx * 2 + 1] = __halves2half2(hi[2], hi[3]);
    pl[idx * 2 + 0] = __halves2half2(lo[0], lo[1]);
    pl[idx * 2 + 1] = __halves2half2(lo[2], lo[3]);
}
// pack W1 (4,512,64) -> [N=256][K=512] K-contiguous, fp16
__global__ void pack_b1_kernel(const float* __restrict__ W1) {
    int idx = blockIdx.x * blockDim.x + threadIdx.x;
    if (idx >= H1 * D_IN) return;
    int n = idx >> 9, k = idx & 511;
    int head = n >> 6, j = n & 63;
    g_B1[idx] = __float2half_rn(W1[head * (D_IN * D_HEAD) + k * D_HEAD + j]);
}
// pack W2 (256,64) -> [N=64][K=256] K-contiguous, fp16
__global__ void pack_b2_kernel(const float* __restrict__ W2) {
    int idx = blockIdx.x * blockDim.x + threadIdx.x;
    if (idx >= D_OUT * H1) return;
    int n = idx >> 8, k = idx & 255;
    g_B2[idx] = __float2half_rn(W2[k * D_OUT + n]);
}

// ---------------- HMMA GEMM (cp.async 2-stage, fp16 A-split x fp16 B) -------
// C[M,N] = (Ahi+Alo)[M,K] @ B[N,K]^T ; fp32 accum.
#define BKC 32
#define RS  40   /* padded row stride in fp16 elems */

template <int BM, int BN, int WARPS_M, int WARPS_N, typename OutT>
__global__ void __launch_bounds__(WARPS_M * WARPS_N * 32, 3)
gemm_mma_kernel(const __half* __restrict__ Ahi, const __half* __restrict__ Alo,
                const __half* __restrict__ B,
                OutT* __restrict__ C, int M, int N, int K) {
    constexpr int NT = WARPS_M * WARPS_N * 32;
    constexpr int WM = BM / WARPS_M;           // 32
    constexpr int WN = BN / WARPS_N;           // 32
    constexpr int TM = WM / 16;                // 2
    constexpr int TN2 = WN / 16;               // 2
    constexpr int TN = WN / 8;                 // 4
    constexpr int SA = BM * RS;                // elems per A plane
    constexpr int SB = BN * RS;
    constexpr int STAGE = 2 * SA + SB;         // elems per stage

    extern __shared__ __half sm[];
    const uint32_t smb = smem_u32(sm);

    const int tid = threadIdx.x;
    const int wid = tid >> 5, lane = tid & 31;
    const int wm0 = (wid / WARPS_N) * WM;
    const int wn0 = (wid % WARPS_N) * WN;
    const int m0 = blockIdx.y * BM;
    const int n0 = blockIdx.x * BN;
    const int NC = K / BKC;

    float acc[TM][TN][4];
    #pragma unroll
    for (int i = 0; i < TM; i++)
        #pragma unroll
        for (int j = 0; j < TN; j++)
            #pragma unroll
            for (int q = 0; q < 4; q++) acc[i][j][q] = 0.f;

    auto issue = [&](int c) {
        int st = c & 1;
        int kt = c * BKC;
        uint32_t aH = smb + (uint32_t)(st * STAGE) * 2;
        uint32_t aL = aH + SA * 2;
        uint32_t bS = aL + SA * 2;
        #pragma unroll
        for (int i = tid; i < BM * 4; i += NT) {
            int row = i >> 2, seg = i & 3;
            int gm = m0 + row;
            int sz = (gm < M) ? 16 : 0;
            int gmc = gm < M ? gm : (M - 1);
            size_t gsrc = (size_t)gmc * K + kt + seg * 8;
            uint32_t so = (uint32_t)(row * RS + seg * 8) * 2;
            cpa16(aH + so, Ahi + gsrc, sz);
            cpa16(aL + so, Alo + gsrc, sz);
        }
        #pragma unroll
        for (int i = tid; i < BN * 4; i += NT) {
            int row = i >> 2, seg = i & 3;
            size_t gsrc = (size_t)(n0 + row) * K + kt + seg * 8;
            uint32_t so = (uint32_t)(row * RS + seg * 8) * 2;
            cpa16(bS + so, B + gsrc, 16);
        }
        CPA_COMMIT();
    };

    const int ldRow = lane & 15;
    const int ldCol = (lane >> 4) * 8;

    issue(0);
    for (int c = 0; c < NC; c++) {
        bool more = (c + 1) < NC;
        if (more) issue(c + 1);
        if (more) asm volatile("cp.async.wait_group 1;" ::: "memory");
        else      asm volatile("cp.async.wait_group 0;" ::: "memory");
        __syncthreads();

        int st = c & 1;
        uint32_t aH = smb + (uint32_t)(st * STAGE) * 2;
        uint32_t aL = aH + SA * 2;
        uint32_t bS = aL + SA * 2;

        #pragma unroll
        for (int s = 0; s < 2; s++) {
            const int kb = s * 16;
            uint32_t ah[TM][4], al[TM][4];
            #pragma unroll
            for (int t = 0; t < TM; t++) {
                uint32_t off = (uint32_t)((wm0 + t * 16 + ldRow) * RS + kb + ldCol) * 2;
                ldsm4(ah[t][0], ah[t][1], ah[t][2], ah[t][3], aH + off);
                ldsm4(al[t][0], al[t][1], al[t][2], al[t][3], aL + off);
            }
            uint32_t bf[TN2][4];
            #pragma unroll
            for (int t = 0; t < TN2; t++) {
                uint32_t off = (uint32_t)((wn0 + t * 16 + ldRow) * RS + kb + ldCol) * 2;
                ldsm4(bf[t][0], bf[t][1], bf[t][2], bf[t][3], bS + off);
            }
            #pragma unroll
            for (int i = 0; i < TM; i++) {
                #pragma unroll
                for (int j = 0; j < TN; j++) {
                    int t2 = j >> 1, odd = j & 1;
                    uint32_t b0 = bf[t2][odd], b1 = bf[t2][odd + 2];
                    mma16816h(acc[i][j], ah[i][0], ah[i][1], ah[i][2], ah[i][3], b0, b1);
                    mma16816h(acc[i][j], al[i][0], al[i][1], al[i][2], al[i][3], b0, b1);
                }
            }
        }
        __syncthreads();
    }

    #pragma unroll
    for (int i = 0; i < TM; i++) {
        int r0 = m0 + wm0 + i * 16 + (lane >> 2);
        #pragma unroll
        for (int j = 0; j < TN; j++) {
            int col = n0 + wn0 + j * 8 + (lane & 3) * 2;
            if (r0 < M)
                store_pair(C, (size_t)r0 * N + col, acc[i][j][0], acc[i][j][1]);
            if (r0 + 8 < M)
                store_pair(C, (size_t)(r0 + 8) * N + col, acc[i][j][2], acc[i][j][3]);
        }
    }
}

// ---------------- layer-1 aggregate + ELU -> fp16 hi/lo ---------------------
// block per node, 128 threads, thread handles 2 features (half2 loads).
__global__ void __launch_bounds__(128) agg1_kernel() {
    int node = blockIdx.x;
    int tid = threadIdx.x;
    int beg = g_row_start[node], end = g_row_start[node + 1];
    __shared__ int sd[128];

    const __half2* t1h = (const __half2*)g_t1h;   // row = 128 half2
    float ax = 0.f, ay = 0.f;

    for (int base = beg; base < end; base += 128) {
        int n = min(128, end - base);
        if (tid < n) sd[tid] = g_sorted_dst[base + tid];
        __syncthreads();
        int e = 0;
        for (; e + 4 <= n; e += 4) {
            int d0 = sd[e], d1 = sd[e + 1], d2 = sd[e + 2], d3 = sd[e + 3];
            float2 f0 = __half22float2(t1h[(size_t)d0 * 128 + tid]);
            float2 f1 = __half22float2(t1h[(size_t)d1 * 128 + tid]);
            float2 f2 = __half22float2(t1h[(size_t)d2 * 128 + tid]);
            float2 f3 = __half22float2(t1h[(size_t)d3 * 128 + tid]);
            ax += f0.x + f1.x + f2.x + f3.x;
            ay += f0.y + f1.y + f2.y + f3.y;
        }
        for (; e < n; e++) {
            float2 f = __half22float2(t1h[(size_t)sd[e] * 128 + tid]);
            ax += f.x; ay += f.y;
        }
        __syncthreads();
    }
    int deg = end - beg;
    float inv = deg > 0 ? 1.f / (float)deg : 0.f;
    float o0 = eluf(ax * inv), o1 = eluf(ay * inv);
    __half h0 = __float2half_rn(o0);
    __half h1 = __float2half_rn(o1);
    __half l0 = __float2half_rn(o0 - __half2float(h0));
    __half l1 = __float2half_rn(o1 - __half2float(h1));
    ((__half2*)g_Hhi)[(size_t)node * 128 + tid] = __halves2half2(h0, h1);
    ((__half2*)g_Hlo)[(size_t)node * 128 + tid] = __halves2half2(l0, l1);
}

// ---------------- layer-2 aggregate (block per node, 64 threads) ------------
__global__ void __launch_bounds__(64) agg2_kernel(float* __restrict__ out) {
    int node = blockIdx.x;
    int tid = threadIdx.x;
    int beg = g_row_start[node], end = g_row_start[node + 1];
    __shared__ int sd[64];

    float a = 0.f;
    for (int base = beg; base < end; base += 64) {
        int n = min(64, end - base);
        if (tid < n) sd[tid] = g_sorted_dst[base + tid];
        __syncthreads();
        int e = 0;
        for (; e + 4 <= n; e += 4) {
            int d0 = sd[e], d1 = sd[e + 1], d2 = sd[e + 2], d3 = sd[e + 3];
            float v0 = g_t2[(size_t)d0 * D_OUT + tid];
            float v1 = g_t2[(size_t)d1 * D_OUT + tid];
            float v2 = g_t2[(size_t)d2 * D_OUT + tid];
            float v3 = g_t2[(size_t)d3 * D_OUT + tid];
            a += v0 + v1 + v2 + v3;
        }
        for (; e < n; e++) a += g_t2[(size_t)sd[e] * D_OUT + tid];
        __syncthreads();
    }
    int deg = end - beg;
    float inv = deg > 0 ? 1.f / (float)deg : 0.f;
    out[(size_t)node * D_OUT + tid] = a * inv;
}

// ---------------- launch ----------------------------------------------------
extern "C" void kernel_launch(void* const* d_in, const int* in_sizes, int n_in,
                              void* d_out, int out_size) {
    const float* X  = (const float*)d_in[0];
    const int*   ei = (const int*)d_in[1];
    const float* W1 = (const float*)d_in[2];
    const float* W2 = (const float*)d_in[3];
    float* out = (float*)d_out;

    void* p;
    cudaGetSymbolAddress(&p, g_t1h); __half* t1 = (__half*)p;
    cudaGetSymbolAddress(&p, g_t2);  float* t2 = (float*)p;
    cudaGetSymbolAddress(&p, g_Xhi); __half* Xhi = (__half*)p;
    cudaGetSymbolAddress(&p, g_Xlo); __half* Xlo = (__half*)p;
    cudaGetSymbolAddress(&p, g_Hhi); __half* Hhi = (__half*)p;
    cudaGetSymbolAddress(&p, g_Hlo); __half* Hlo = (__half*)p;
    cudaGetSymbolAddress(&p, g_B1);  __half* B1 = (__half*)p;
    cudaGetSymbolAddress(&p, g_B2);  __half* B2 = (__half*)p;

    // smem: stage = (2*128*RS + 64*RS)*2 bytes ; 2 stages = 51200
    const int SMEM = 2 * (2 * 128 * RS + 64 * RS) * 2;
    cudaFuncSetAttribute((const void*)gemm_mma_kernel<128, 64, 4, 2, __half>,
                         cudaFuncAttributeMaxDynamicSharedMemorySize, SMEM);
    cudaFuncSetAttribute((const void*)gemm_mma_kernel<128, 64, 4, 2, float>,
                         cudaFuncAttributeMaxDynamicSharedMemorySize, SMEM);

    // --- conversions first so gemm1 lands in the ncu profiling slot (#4) ---
    conv_x_kernel<<<(N_NODES * D_IN / 4 + 255) / 256, 256>>>(X);
    pack_b1_kernel<<<(H1 * D_IN + 255) / 256, 256>>>(W1);
    pack_b2_kernel<<<(D_OUT * H1 + 255) / 256, 256>>>(W2);

    // Layer 1 GEMM (HMMA): t1h = X @ B1^T   [50000,512] x [256,512]
    {
        dim3 grid(H1 / 64, (N_NODES + 127) / 128);
        gemm_mma_kernel<128, 64, 4, 2, __half><<<grid, 256, SMEM>>>(
            Xhi, Xlo, B1, t1, N_NODES, H1, D_IN);
    }

    // CSR build
    zero_counts_kernel<<<(N_NODES + 255) / 256, 256>>>();
    hist_kernel<<<(N_EDGES + 255) / 256, 256>>>(ei);
    scan1_kernel<<<SCAN_NB, 1024>>>();
    scan2_kernel<<<1, 64>>>();
    scan3_kernel<<<SCAN_NB, 1024>>>();
    scatter_kernel<<<(N_EDGES + 255) / 256, 256>>>(ei);

    agg1_kernel<<<N_NODES, 128>>>();

    // Layer 2 GEMM (HMMA): t2 = h @ B2^T   [50000,256] x [64,256]
    {
        dim3 grid(1, (N_NODES + 127) / 128);
        gemm_mma_kernel<128, 64, 4, 2, float><<<grid, 256, SMEM>>>(
            Hhi, Hlo, B2, t2, N_NODES, D_OUT, H1);
    }

    agg2_kernel<<<N_NODES, 64>>>(out);
}

// round 6
// speedup vs baseline: 2.1570x; 1.2203x over previous
#include <cuda_runtime.h>
#include <cuda_fp16.h>
#include <math.h>
#include <stdint.h>

#define N_NODES 50000
#define N_EDGES 1600000
#define D_IN    512
#define D_HEAD  64
#define H1      256   /* 4 heads * 64 */
#define D_OUT   64

// ---------------- scratch (device globals; no allocation allowed) ----------
__device__ __half g_t1h[(size_t)N_NODES * H1];          // X @ W1cat (fp16)
__device__ float  g_t2[(size_t)N_NODES * D_OUT];        // h @ W2 (fp32)
__device__ __half g_X16[(size_t)N_NODES * D_IN];        // fp16 X
__device__ __half g_H16[(size_t)N_NODES * H1];          // elu(agg1) fp16
__device__ __half g_B1[H1 * D_IN];                      // W1 packed [N=256][K=512] fp16
__device__ __half g_B2[D_OUT * H1];                     // W2 packed [N=64][K=256] fp16
__device__ int   g_counts[N_NODES];
__device__ int   g_row_start[N_NODES + 1];
__device__ int   g_cursor[N_NODES];
__device__ int   g_sorted_dst[N_EDGES];
__device__ int   g_bsums[64];
__device__ int   g_boff[64];

// ---------------- helpers ---------------------------------------------------
__device__ __forceinline__ float eluf(float x) { return x > 0.f ? x : expm1f(x); }
__device__ __forceinline__ uint32_t smem_u32(const void* p) {
    uint32_t a;
    asm("{ .reg .u64 t; cvta.to.shared.u64 t, %1; cvt.u32.u64 %0, t; }" : "=r"(a) : "l"(p));
    return a;
}
__device__ __forceinline__ void ldsm4(uint32_t& r0, uint32_t& r1, uint32_t& r2, uint32_t& r3,
                                      uint32_t addr) {
    asm volatile("ldmatrix.sync.aligned.m8n8.x4.shared.b16 {%0,%1,%2,%3}, [%4];"
                 : "=r"(r0), "=r"(r1), "=r"(r2), "=r"(r3) : "r"(addr));
}
__device__ __forceinline__ void mma16816h(float* c, uint32_t a0, uint32_t a1, uint32_t a2,
                                          uint32_t a3, uint32_t b0, uint32_t b1) {
    asm volatile(
        "mma.sync.aligned.m16n8k16.row.col.f32.f16.f16.f32 "
        "{%0,%1,%2,%3}, {%4,%5,%6,%7}, {%8,%9}, {%0,%1,%2,%3};"
        : "+f"(c[0]), "+f"(c[1]), "+f"(c[2]), "+f"(c[3])
        : "r"(a0), "r"(a1), "r"(a2), "r"(a3), "r"(b0), "r"(b1));
}
__device__ __forceinline__ void cpa16(uint32_t saddr, const void* gaddr, int sz) {
    asm volatile("cp.async.cg.shared.global [%0], [%1], 16, %2;"
                 :: "r"(saddr), "l"(gaddr), "r"(sz));
}
#define CPA_COMMIT() asm volatile("cp.async.commit_group;" ::: "memory")

__device__ __forceinline__ void store_pair(float* C, size_t off, float x, float y) {
    *(float2*)(C + off) = make_float2(x, y);
}
__device__ __forceinline__ void store_pair(__half* C, size_t off, float x, float y) {
    *(__half2*)(C + off) = __floats2half2_rn(x, y);
}

// ---------------- CSR build: histogram -> 3-phase scan -> scatter -----------
__global__ void zero_counts_kernel() {
    int i = blockIdx.x * blockDim.x + threadIdx.x;
    if (i < N_NODES) g_counts[i] = 0;
}
__global__ void hist_kernel(const int* __restrict__ ei) {
    int t = blockIdx.x * blockDim.x + threadIdx.x;
    if (t < N_EDGES / 4) {
        int4 s = ((const int4*)ei)[t];
        atomicAdd(&g_counts[s.x], 1);
        atomicAdd(&g_counts[s.y], 1);
        atomicAdd(&g_counts[s.z], 1);
        atomicAdd(&g_counts[s.w], 1);
    }
}
#define SCAN_NB 49   /* ceil(50000/1024) */
__global__ void __launch_bounds__(1024) scan1_kernel() {
    __shared__ int wsum[32];
    int tid = threadIdx.x, lane = tid & 31, wid = tid >> 5;
    int i = blockIdx.x * 1024 + tid;
    int v = (i < N_NODES) ? g_counts[i] : 0;
    int x = v;
    #pragma unroll
    for (int o = 1; o < 32; o <<= 1) {
        int t = __shfl_up_sync(0xffffffffu, x, o);
        if (lane >= o) x += t;
    }
    if (lane == 31) wsum[wid] = x;
    __syncthreads();
    if (wid == 0) {
        int s = wsum[lane];
        #pragma unroll
        for (int o = 1; o < 32; o <<= 1) {
            int t = __shfl_up_sync(0xffffffffu, s, o);
            if (lane >= o) s += t;
        }
        wsum[lane] = s;
    }
    __syncthreads();
    int boff = (wid > 0) ? wsum[wid - 1] : 0;
    int incl = x + boff;
    if (i < N_NODES) g_row_start[i] = incl - v;
    if (tid == 1023) g_bsums[blockIdx.x] = incl;
}
__global__ void scan2_kernel() {
    __shared__ int sh[64];
    int t = threadIdx.x;
    int v = (t < SCAN_NB) ? g_bsums[t] : 0;
    sh[t] = v;
    __syncthreads();
    #pragma unroll
    for (int o = 1; o < 64; o <<= 1) {
        int val = (t >= o) ? sh[t - o] : 0;
        __syncthreads();
        sh[t] += val;
        __syncthreads();
    }
    if (t < SCAN_NB) g_boff[t] = sh[t] - v;
}
__global__ void __launch_bounds__(1024) scan3_kernel() {
    int i = blockIdx.x * 1024 + threadIdx.x;
    if (i < N_NODES) {
        int rs = g_row_start[i] + g_boff[blockIdx.x];
        g_row_start[i] = rs;
        g_cursor[i] = rs;
    }
    if (i == 0) g_row_start[N_NODES] = N_EDGES;
}
__global__ void scatter_kernel(const int* __restrict__ ei) {
    int t = blockIdx.x * blockDim.x + threadIdx.x;
    if (t < N_EDGES / 4) {
        int4 s = ((const int4*)ei)[t];
        int4 d = ((const int4*)(ei + N_EDGES))[t];
        int p0 = atomicAdd(&g_cursor[s.x], 1);
        int p1 = atomicAdd(&g_cursor[s.y], 1);
        int p2 = atomicAdd(&g_cursor[s.z], 1);
        int p3 = atomicAdd(&g_cursor[s.w], 1);
        g_sorted_dst[p0] = d.x;
        g_sorted_dst[p1] = d.y;
        g_sorted_dst[p2] = d.z;
        g_sorted_dst[p3] = d.w;
    }
}

// ---------------- fp16 conversions ------------------------------------------
__global__ void conv_x_kernel(const float* __restrict__ X) {
    int idx = blockIdx.x * blockDim.x + threadIdx.x;    // one float4 per thread
    if (idx >= N_NODES * D_IN / 4) return;
    float4 v = ((const float4*)X)[idx];
    __half2* ph = (__half2*)g_X16;
    ph[idx * 2 + 0] = __floats2half2_rn(v.x, v.y);
    ph[idx * 2 + 1] = __floats2half2_rn(v.z, v.w);
}
// pack W1 (4,512,64) -> [N=256][K=512] K-contiguous, fp16
__global__ void pack_b1_kernel(const float* __restrict__ W1) {
    int idx = blockIdx.x * blockDim.x + threadIdx.x;
    if (idx >= H1 * D_IN) return;
    int n = idx >> 9, k = idx & 511;
    int head = n >> 6, j = n & 63;
    g_B1[idx] = __float2half_rn(W1[head * (D_IN * D_HEAD) + k * D_HEAD + j]);
}
// pack W2 (256,64) -> [N=64][K=256] K-contiguous, fp16
__global__ void pack_b2_kernel(const float* __restrict__ W2) {
    int idx = blockIdx.x * blockDim.x + threadIdx.x;
    if (idx >= D_OUT * H1) return;
    int n = idx >> 8, k = idx & 255;
    g_B2[idx] = __float2half_rn(W2[k * D_OUT + n]);
}

// ---------------- HMMA GEMM (cp.async 2-stage, fp16 x fp16, fp32 accum) -----
// C[M,N] = A[M,K] @ B[N,K]^T
#define BKC 64
#define RS  72   /* padded row stride in fp16 elems (64 + 8) */

template <int BM, int BN, int WARPS_M, int WARPS_N, typename OutT>
__global__ void __launch_bounds__(WARPS_M * WARPS_N * 32, 3)
gemm_mma_kernel(const __half* __restrict__ A, const __half* __restrict__ B,
                OutT* __restrict__ C, int M, int N, int K) {
    constexpr int NT = WARPS_M * WARPS_N * 32;
    constexpr int WM = BM / WARPS_M;           // 32
    constexpr int WN = BN / WARPS_N;           // 32
    constexpr int TM = WM / 16;                // 2
    constexpr int TN2 = WN / 16;               // 2
    constexpr int TN = WN / 8;                 // 4
    constexpr int SA = BM * RS;                // elems per A plane
    constexpr int SB = BN * RS;
    constexpr int STAGE = SA + SB;             // elems per stage

    extern __shared__ __half sm[];
    const uint32_t smb = smem_u32(sm);

    const int tid = threadIdx.x;
    const int wid = tid >> 5, lane = tid & 31;
    const int wm0 = (wid / WARPS_N) * WM;
    const int wn0 = (wid % WARPS_N) * WN;
    const int m0 = blockIdx.y * BM;
    const int n0 = blockIdx.x * BN;
    const int NC = K / BKC;

    float acc[TM][TN][4];
    #pragma unroll
    for (int i = 0; i < TM; i++)
        #pragma unroll
        for (int j = 0; j < TN; j++)
            #pragma unroll
            for (int q = 0; q < 4; q++) acc[i][j][q] = 0.f;

    auto issue = [&](int c) {
        int st = c & 1;
        int kt = c * BKC;
        uint32_t aS = smb + (uint32_t)(st * STAGE) * 2;
        uint32_t bS = aS + SA * 2;
        #pragma unroll
        for (int i = tid; i < BM * 8; i += NT) {
            int row = i >> 3, seg = i & 7;
            int gm = m0 + row;
            int sz = (gm < M) ? 16 : 0;
            int gmc = gm < M ? gm : (M - 1);
            size_t gsrc = (size_t)gmc * K + kt + seg * 8;
            uint32_t so = (uint32_t)(row * RS + seg * 8) * 2;
            cpa16(aS + so, A + gsrc, sz);
        }
        #pragma unroll
        for (int i = tid; i < BN * 8; i += NT) {
            int row = i >> 3, seg = i & 7;
            size_t gsrc = (size_t)(n0 + row) * K + kt + seg * 8;
            uint32_t so = (uint32_t)(row * RS + seg * 8) * 2;
            cpa16(bS + so, B + gsrc, 16);
        }
        CPA_COMMIT();
    };

    const int ldRow = lane & 15;
    const int ldCol = (lane >> 4) * 8;

    issue(0);
    for (int c = 0; c < NC; c++) {
        bool more = (c + 1) < NC;
        if (more) issue(c + 1);
        if (more) asm volatile("cp.async.wait_group 1;" ::: "memory");
        else      asm volatile("cp.async.wait_group 0;" ::: "memory");
        __syncthreads();

        int st = c & 1;
        uint32_t aS = smb + (uint32_t)(st * STAGE) * 2;
        uint32_t bS = aS + SA * 2;

        #pragma unroll
        for (int s = 0; s < 4; s++) {              // four k16 steps
            const int kb = s * 16;
            uint32_t af[TM][4];
            #pragma unroll
            for (int t = 0; t < TM; t++) {
                uint32_t off = (uint32_t)((wm0 + t * 16 + ldRow) * RS + kb + ldCol) * 2;
                ldsm4(af[t][0], af[t][1], af[t][2], af[t][3], aS + off);
            }
            uint32_t bf[TN2][4];
            #pragma unroll
            for (int t = 0; t < TN2; t++) {
                uint32_t off = (uint32_t)((wn0 + t * 16 + ldRow) * RS + kb + ldCol) * 2;
                ldsm4(bf[t][0], bf[t][1], bf[t][2], bf[t][3], bS + off);
            }
            #pragma unroll
            for (int i = 0; i < TM; i++) {
                #pragma unroll
                for (int j = 0; j < TN; j++) {
                    int t2 = j >> 1, odd = j & 1;
                    mma16816h(acc[i][j], af[i][0], af[i][1], af[i][2], af[i][3],
                              bf[t2][odd], bf[t2][odd + 2]);
                }
            }
        }
        __syncthreads();
    }

    #pragma unroll
    for (int i = 0; i < TM; i++) {
        int r0 = m0 + wm0 + i * 16 + (lane >> 2);
        #pragma unroll
        for (int j = 0; j < TN; j++) {
            int col = n0 + wn0 + j * 8 + (lane & 3) * 2;
            if (r0 < M)
                store_pair(C, (size_t)r0 * N + col, acc[i][j][0], acc[i][j][1]);
            if (r0 + 8 < M)
                store_pair(C, (size_t)(r0 + 8) * N + col, acc[i][j][2], acc[i][j][3]);
        }
    }
}

// ---------------- layer-1 aggregate + ELU -> fp16 -------------------------
// block per node, 128 threads, thread handles 2 features (half2 loads).
__global__ void __launch_bounds__(128) agg1_kernel() {
    int node = blockIdx.x;
    int tid = threadIdx.x;
    int beg = g_row_start[node], end = g_row_start[node + 1];
    __shared__ int sd[128];

    const __half2* t1h = (const __half2*)g_t1h;   // row = 128 half2
    float ax = 0.f, ay = 0.f;

    for (int base = beg; base < end; base += 128) {
        int n = min(128, end - base);
        if (tid < n) sd[tid] = g_sorted_dst[base + tid];
        __syncthreads();
        int e = 0;
        for (; e + 4 <= n; e += 4) {
            int d0 = sd[e], d1 = sd[e + 1], d2 = sd[e + 2], d3 = sd[e + 3];
            float2 f0 = __half22float2(t1h[(size_t)d0 * 128 + tid]);
            float2 f1 = __half22float2(t1h[(size_t)d1 * 128 + tid]);
            float2 f2 = __half22float2(t1h[(size_t)d2 * 128 + tid]);
            float2 f3 = __half22float2(t1h[(size_t)d3 * 128 + tid]);
            ax += f0.x + f1.x + f2.x + f3.x;
            ay += f0.y + f1.y + f2.y + f3.y;
        }
        for (; e < n; e++) {
            float2 f = __half22float2(t1h[(size_t)sd[e] * 128 + tid]);
            ax += f.x; ay += f.y;
        }
        __syncthreads();
    }
    int deg = end - beg;
    float inv = deg > 0 ? 1.f / (float)deg : 0.f;
    float o0 = eluf(ax * inv), o1 = eluf(ay * inv);
    ((__half2*)g_H16)[(size_t)node * 128 + tid] = __floats2half2_rn(o0, o1);
}

// ---------------- layer-2 aggregate (block per node, 64 threads) ------------
__global__ void __launch_bounds__(64) agg2_kernel(float* __restrict__ out) {
    int node = blockIdx.x;
    int tid = threadIdx.x;
    int beg = g_row_start[node], end = g_row_start[node + 1];
    __shared__ int sd[64];

    float a = 0.f;
    for (int base = beg; base < end; base += 64) {
        int n = min(64, end - base);
        if (tid < n) sd[tid] = g_sorted_dst[base + tid];
        __syncthreads();
        int e = 0;
        for (; e + 4 <= n; e += 4) {
            int d0 = sd[e], d1 = sd[e + 1], d2 = sd[e + 2], d3 = sd[e + 3];
            float v0 = g_t2[(size_t)d0 * D_OUT + tid];
            float v1 = g_t2[(size_t)d1 * D_OUT + tid];
            float v2 = g_t2[(size_t)d2 * D_OUT + tid];
            float v3 = g_t2[(size_t)d3 * D_OUT + tid];
            a += v0 + v1 + v2 + v3;
        }
        for (; e < n; e++) a += g_t2[(size_t)sd[e] * D_OUT + tid];
        __syncthreads();
    }
    int deg = end - beg;
    float inv = deg > 0 ? 1.f / (float)deg : 0.f;
    out[(size_t)node * D_OUT + tid] = a * inv;
}

// ---------------- launch ----------------------------------------------------
extern "C" void kernel_launch(void* const* d_in, const int* in_sizes, int n_in,
                              void* d_out, int out_size) {
    const float* X  = (const float*)d_in[0];
    const int*   ei = (const int*)d_in[1];
    const float* W1 = (const float*)d_in[2];
    const float* W2 = (const float*)d_in[3];
    float* out = (float*)d_out;

    void* p;
    cudaGetSymbolAddress(&p, g_t1h); __half* t1 = (__half*)p;
    cudaGetSymbolAddress(&p, g_t2);  float* t2 = (float*)p;
    cudaGetSymbolAddress(&p, g_X16); __half* X16 = (__half*)p;
    cudaGetSymbolAddress(&p, g_H16); __half* H16 = (__half*)p;
    cudaGetSymbolAddress(&p, g_B1);  __half* B1 = (__half*)p;
    cudaGetSymbolAddress(&p, g_B2);  __half* B2 = (__half*)p;

    // smem: stage = (128+64)*RS*2 bytes ; 2 stages = 55296
    const int SMEM = 2 * (128 + 64) * RS * 2;
    cudaFuncSetAttribute((const void*)gemm_mma_kernel<128, 64, 4, 2, __half>,
                         cudaFuncAttributeMaxDynamicSharedMemorySize, SMEM);
    cudaFuncSetAttribute((const void*)gemm_mma_kernel<128, 64, 4, 2, float>,
                         cudaFuncAttributeMaxDynamicSharedMemorySize, SMEM);

    // --- conversions first so gemm1 lands in the ncu profiling slot (#4) ---
    conv_x_kernel<<<(N_NODES * D_IN / 4 + 255) / 256, 256>>>(X);
    pack_b1_kernel<<<(H1 * D_IN + 255) / 256, 256>>>(W1);
    pack_b2_kernel<<<(D_OUT * H1 + 255) / 256, 256>>>(W2);

    // Layer 1 GEMM (HMMA): t1h = X16 @ B1^T   [50000,512] x [256,512]
    {
        dim3 grid(H1 / 64, (N_NODES + 127) / 128);
        gemm_mma_kernel<128, 64, 4, 2, __half><<<grid, 256, SMEM>>>(
            X16, B1, t1, N_NODES, H1, D_IN);
    }

    // CSR build
    zero_counts_kernel<<<(N_NODES + 255) / 256, 256>>>();
    hist_kernel<<<(N_EDGES / 4 + 255) / 256, 256>>>(ei);
    scan1_kernel<<<SCAN_NB, 1024>>>();
    scan2_kernel<<<1, 64>>>();
    scan3_kernel<<<SCAN_NB, 1024>>>();
    scatter_kernel<<<(N_EDGES / 4 + 255) / 256, 256>>>(ei);

    agg1_kernel<<<N_NODES, 128>>>();

    // Layer 2 GEMM (HMMA): t2 = H16 @ B2^T   [50000,256] x [64,256]
    {
        dim3 grid(1, (N_NODES + 127) / 128);
        gemm_mma_kernel<128, 64, 4, 2, float><<<grid, 256, SMEM>>>(
            H16, B2, t2, N_NODES, D_OUT, H1);
    }

    agg2_kernel<<<N_NODES, 64>>>(out);
}

// round 7
// speedup vs baseline: 2.3239x; 1.0774x over previous
#include <cuda_runtime.h>
#include <cuda_fp16.h>
#include <math.h>
#include <stdint.h>

#define N_NODES 50000
#define N_EDGES 1600000
#define D_IN    512
#define D_HEAD  64
#define H1      256   /* 4 heads * 64 */
#define D_OUT   64

// ---------------- scratch (device globals; no allocation allowed) ----------
__device__ __half g_t1h[(size_t)N_NODES * H1];          // X @ W1cat (fp16)
__device__ __half g_t2h[(size_t)N_NODES * D_OUT];       // h @ W2 (fp16)
__device__ __half g_X16[(size_t)N_NODES * D_IN];        // fp16 X
__device__ __half g_H16[(size_t)N_NODES * H1];          // elu(agg1) fp16
__device__ __half g_B1[H1 * D_IN];                      // W1 packed [N=256][K=512] fp16
__device__ __half g_B2[D_OUT * H1];                     // W2 packed [N=64][K=256] fp16
__device__ int   g_counts[N_NODES];
__device__ int   g_row_start[N_NODES + 1];
__device__ int   g_cursor[N_NODES];
__device__ int   g_sorted_dst[N_EDGES];
__device__ int   g_bsums[64];
__device__ int   g_boff[64];

// ---------------- helpers ---------------------------------------------------
__device__ __forceinline__ float eluf(float x) { return x > 0.f ? x : expm1f(x); }
__device__ __forceinline__ uint32_t smem_u32(const void* p) {
    uint32_t a;
    asm("{ .reg .u64 t; cvta.to.shared.u64 t, %1; cvt.u32.u64 %0, t; }" : "=r"(a) : "l"(p));
    return a;
}
__device__ __forceinline__ void ldsm4(uint32_t& r0, uint32_t& r1, uint32_t& r2, uint32_t& r3,
                                      uint32_t addr) {
    asm volatile("ldmatrix.sync.aligned.m8n8.x4.shared.b16 {%0,%1,%2,%3}, [%4];"
                 : "=r"(r0), "=r"(r1), "=r"(r2), "=r"(r3) : "r"(addr));
}
__device__ __forceinline__ void mma16816h(float* c, uint32_t a0, uint32_t a1, uint32_t a2,
                                          uint32_t a3, uint32_t b0, uint32_t b1) {
    asm volatile(
        "mma.sync.aligned.m16n8k16.row.col.f32.f16.f16.f32 "
        "{%0,%1,%2,%3}, {%4,%5,%6,%7}, {%8,%9}, {%0,%1,%2,%3};"
        : "+f"(c[0]), "+f"(c[1]), "+f"(c[2]), "+f"(c[3])
        : "r"(a0), "r"(a1), "r"(a2), "r"(a3), "r"(b0), "r"(b1));
}
__device__ __forceinline__ void cpa16(uint32_t saddr, const void* gaddr, int sz) {
    asm volatile("cp.async.cg.shared.global [%0], [%1], 16, %2;"
                 :: "r"(saddr), "l"(gaddr), "r"(sz));
}
#define CPA_COMMIT() asm volatile("cp.async.commit_group;" ::: "memory")

__device__ __forceinline__ void store_pair(float* C, size_t off, float x, float y) {
    *(float2*)(C + off) = make_float2(x, y);
}
__device__ __forceinline__ void store_pair(__half* C, size_t off, float x, float y) {
    *(__half2*)(C + off) = __floats2half2_rn(x, y);
}

// ---------------- CSR build: histogram -> 3-phase scan -> scatter -----------
__global__ void zero_counts_kernel() {
    int i = blockIdx.x * blockDim.x + threadIdx.x;
    if (i < N_NODES) g_counts[i] = 0;
}
__global__ void hist_kernel(const int* __restrict__ ei) {
    int t = blockIdx.x * blockDim.x + threadIdx.x;
    if (t < N_EDGES / 4) {
        int4 s = ((const int4*)ei)[t];
        atomicAdd(&g_counts[s.x], 1);
        atomicAdd(&g_counts[s.y], 1);
        atomicAdd(&g_counts[s.z], 1);
        atomicAdd(&g_counts[s.w], 1);
    }
}
#define SCAN_NB 49   /* ceil(50000/1024) */
__global__ void __launch_bounds__(1024) scan1_kernel() {
    __shared__ int wsum[32];
    int tid = threadIdx.x, lane = tid & 31, wid = tid >> 5;
    int i = blockIdx.x * 1024 + tid;
    int v = (i < N_NODES) ? g_counts[i] : 0;
    int x = v;
    #pragma unroll
    for (int o = 1; o < 32; o <<= 1) {
        int t = __shfl_up_sync(0xffffffffu, x, o);
        if (lane >= o) x += t;
    }
    if (lane == 31) wsum[wid] = x;
    __syncthreads();
    if (wid == 0) {
        int s = wsum[lane];
        #pragma unroll
        for (int o = 1; o < 32; o <<= 1) {
            int t = __shfl_up_sync(0xffffffffu, s, o);
            if (lane >= o) s += t;
        }
        wsum[lane] = s;
    }
    __syncthreads();
    int boff = (wid > 0) ? wsum[wid - 1] : 0;
    int incl = x + boff;
    if (i < N_NODES) g_row_start[i] = incl - v;
    if (tid == 1023) g_bsums[blockIdx.x] = incl;
}
__global__ void scan2_kernel() {
    __shared__ int sh[64];
    int t = threadIdx.x;
    int v = (t < SCAN_NB) ? g_bsums[t] : 0;
    sh[t] = v;
    __syncthreads();
    #pragma unroll
    for (int o = 1; o < 64; o <<= 1) {
        int val = (t >= o) ? sh[t - o] : 0;
        __syncthreads();
        sh[t] += val;
        __syncthreads();
    }
    if (t < SCAN_NB) g_boff[t] = sh[t] - v;
}
__global__ void __launch_bounds__(1024) scan3_kernel() {
    int i = blockIdx.x * 1024 + threadIdx.x;
    if (i < N_NODES) {
        int rs = g_row_start[i] + g_boff[blockIdx.x];
        g_row_start[i] = rs;
        g_cursor[i] = rs;
    }
    if (i == 0) g_row_start[N_NODES] = N_EDGES;
}
__global__ void scatter_kernel(const int* __restrict__ ei) {
    int t = blockIdx.x * blockDim.x + threadIdx.x;
    if (t < N_EDGES / 4) {
        int4 s = ((const int4*)ei)[t];
        int4 d = ((const int4*)(ei + N_EDGES))[t];
        int p0 = atomicAdd(&g_cursor[s.x], 1);
        int p1 = atomicAdd(&g_cursor[s.y], 1);
        int p2 = atomicAdd(&g_cursor[s.z], 1);
        int p3 = atomicAdd(&g_cursor[s.w], 1);
        g_sorted_dst[p0] = d.x;
        g_sorted_dst[p1] = d.y;
        g_sorted_dst[p2] = d.z;
        g_sorted_dst[p3] = d.w;
    }
}

// ---------------- fp16 conversions ------------------------------------------
__global__ void conv_x_kernel(const float* __restrict__ X) {
    int idx = blockIdx.x * blockDim.x + threadIdx.x;    // one float4 per thread
    if (idx >= N_NODES * D_IN / 4) return;
    float4 v = ((const float4*)X)[idx];
    __half2* ph = (__half2*)g_X16;
    ph[idx * 2 + 0] = __floats2half2_rn(v.x, v.y);
    ph[idx * 2 + 1] = __floats2half2_rn(v.z, v.w);
}
__global__ void pack_b1_kernel(const float* __restrict__ W1) {
    int idx = blockIdx.x * blockDim.x + threadIdx.x;
    if (idx >= H1 * D_IN) return;
    int n = idx >> 9, k = idx & 511;
    int head = n >> 6, j = n & 63;
    g_B1[idx] = __float2half_rn(W1[head * (D_IN * D_HEAD) + k * D_HEAD + j]);
}
__global__ void pack_b2_kernel(const float* __restrict__ W2) {
    int idx = blockIdx.x * blockDim.x + threadIdx.x;
    if (idx >= D_OUT * H1) return;
    int n = idx >> 8, k = idx & 255;
    g_B2[idx] = __float2half_rn(W2[k * D_OUT + n]);
}

// ---------------- HMMA GEMM (cp.async 2-stage, fp16 x fp16, fp32 accum) -----
#define BKC 64
#define RS  72   /* padded row stride in fp16 elems (64 + 8) */

template <int BM, int BN, int WARPS_M, int WARPS_N, typename OutT>
__global__ void __launch_bounds__(WARPS_M * WARPS_N * 32, 3)
gemm_mma_kernel(const __half* __restrict__ A, const __half* __restrict__ B,
                OutT* __restrict__ C, int M, int N, int K) {
    constexpr int NT = WARPS_M * WARPS_N * 32;
    constexpr int WM = BM / WARPS_M;           // 32
    constexpr int WN = BN / WARPS_N;           // 32
    constexpr int TM = WM / 16;                // 2
    constexpr int TN2 = WN / 16;               // 2
    constexpr int TN = WN / 8;                 // 4
    constexpr int SA = BM * RS;
    constexpr int SB = BN * RS;
    constexpr int STAGE = SA + SB;

    extern __shared__ __half sm[];
    const uint32_t smb = smem_u32(sm);

    const int tid = threadIdx.x;
    const int wid = tid >> 5, lane = tid & 31;
    const int wm0 = (wid / WARPS_N) * WM;
    const int wn0 = (wid % WARPS_N) * WN;
    const int m0 = blockIdx.y * BM;
    const int n0 = blockIdx.x * BN;
    const int NC = K / BKC;

    float acc[TM][TN][4];
    #pragma unroll
    for (int i = 0; i < TM; i++)
        #pragma unroll
        for (int j = 0; j < TN; j++)
            #pragma unroll
            for (int q = 0; q < 4; q++) acc[i][j][q] = 0.f;

    auto issue = [&](int c) {
        int st = c & 1;
        int kt = c * BKC;
        uint32_t aS = smb + (uint32_t)(st * STAGE) * 2;
        uint32_t bS = aS + SA * 2;
        #pragma unroll
        for (int i = tid; i < BM * 8; i += NT) {
            int row = i >> 3, seg = i & 7;
            int gm = m0 + row;
            int sz = (gm < M) ? 16 : 0;
            int gmc = gm < M ? gm : (M - 1);
            size_t gsrc = (size_t)gmc * K + kt + seg * 8;
            uint32_t so = (uint32_t)(row * RS + seg * 8) * 2;
            cpa16(aS + so, A + gsrc, sz);
        }
        #pragma unroll
        for (int i = tid; i < BN * 8; i += NT) {
            int row = i >> 3, seg = i & 7;
            size_t gsrc = (size_t)(n0 + row) * K + kt + seg * 8;
            uint32_t so = (uint32_t)(row * RS + seg * 8) * 2;
            cpa16(bS + so, B + gsrc, 16);
        }
        CPA_COMMIT();
    };

    const int ldRow = lane & 15;
    const int ldCol = (lane >> 4) * 8;

    issue(0);
    for (int c = 0; c < NC; c++) {
        bool more = (c + 1) < NC;
        if (more) issue(c + 1);
        if (more) asm volatile("cp.async.wait_group 1;" ::: "memory");
        else      asm volatile("cp.async.wait_group 0;" ::: "memory");
        __syncthreads();

        int st = c & 1;
        uint32_t aS = smb + (uint32_t)(st * STAGE) * 2;
        uint32_t bS = aS + SA * 2;

        #pragma unroll
        for (int s = 0; s < 4; s++) {
            const int kb = s * 16;
            uint32_t af[TM][4];
            #pragma unroll
            for (int t = 0; t < TM; t++) {
                uint32_t off = (uint32_t)((wm0 + t * 16 + ldRow) * RS + kb + ldCol) * 2;
                ldsm4(af[t][0], af[t][1], af[t][2], af[t][3], aS + off);
            }
            uint32_t bf[TN2][4];
            #pragma unroll
            for (int t = 0; t < TN2; t++) {
                uint32_t off = (uint32_t)((wn0 + t * 16 + ldRow) * RS + kb + ldCol) * 2;
                ldsm4(bf[t][0], bf[t][1], bf[t][2], bf[t][3], bS + off);
            }
            #pragma unroll
            for (int i = 0; i < TM; i++) {
                #pragma unroll
                for (int j = 0; j < TN; j++) {
                    int t2 = j >> 1, odd = j & 1;
                    mma16816h(acc[i][j], af[i][0], af[i][1], af[i][2], af[i][3],
                              bf[t2][odd], bf[t2][odd + 2]);
                }
            }
        }
        __syncthreads();
    }

    #pragma unroll
    for (int i = 0; i < TM; i++) {
        int r0 = m0 + wm0 + i * 16 + (lane >> 2);
        #pragma unroll
        for (int j = 0; j < TN; j++) {
            int col = n0 + wn0 + j * 8 + (lane & 3) * 2;
            if (r0 < M)
                store_pair(C, (size_t)r0 * N + col, acc[i][j][0], acc[i][j][1]);
            if (r0 + 8 < M)
                store_pair(C, (size_t)(r0 + 8) * N + col, acc[i][j][2], acc[i][j][3]);
        }
    }
}

// ---------------- layer-1 aggregate + ELU -> fp16 ---------------------------
// block per node, 128 threads, thread handles 2 features (half2 loads).
__global__ void __launch_bounds__(128) agg1_kernel() {
    int node = blockIdx.x;
    int tid = threadIdx.x;
    int beg = g_row_start[node], end = g_row_start[node + 1];
    __shared__ int sd[128];

    const __half2* t1h = (const __half2*)g_t1h;   // row = 128 half2
    float ax = 0.f, ay = 0.f;

    for (int base = beg; base < end; base += 128) {
        int n = min(128, end - base);
        if (tid < n) sd[tid] = g_sorted_dst[base + tid];
        __syncthreads();
        int e = 0;
        for (; e + 4 <= n; e += 4) {
            int d0 = sd[e], d1 = sd[e + 1], d2 = sd[e + 2], d3 = sd[e + 3];
            float2 f0 = __half22float2(t1h[(size_t)d0 * 128 + tid]);
            float2 f1 = __half22float2(t1h[(size_t)d1 * 128 + tid]);
            float2 f2 = __half22float2(t1h[(size_t)d2 * 128 + tid]);
            float2 f3 = __half22float2(t1h[(size_t)d3 * 128 + tid]);
            ax += f0.x + f1.x + f2.x + f3.x;
            ay += f0.y + f1.y + f2.y + f3.y;
        }
        for (; e < n; e++) {
            float2 f = __half22float2(t1h[(size_t)sd[e] * 128 + tid]);
            ax += f.x; ay += f.y;
        }
        __syncthreads();
    }
    int deg = end - beg;
    float inv = deg > 0 ? 1.f / (float)deg : 0.f;
    float o0 = eluf(ax * inv), o1 = eluf(ay * inv);
    ((__half2*)g_H16)[(size_t)node * 128 + tid] = __floats2half2_rn(o0, o1);
}

// ---------------- layer-2 aggregate (warp per node, half2 lanes) ------------
__global__ void __launch_bounds__(256) agg2_kernel(float* __restrict__ out) {
    int gw = (blockIdx.x * 256 + threadIdx.x) >> 5;
    int lane = threadIdx.x & 31;
    if (gw >= N_NODES) return;
    int beg = g_row_start[gw], end = g_row_start[gw + 1];

    const __half2* t2h = (const __half2*)g_t2h;   // row = 32 half2
    float ax = 0.f, ay = 0.f;
    for (int eb = beg; eb < end; eb += 32) {
        int n = min(32, end - eb);
        int myd = (lane < n) ? g_sorted_dst[eb + lane] : 0;
        int i = 0;
        for (; i + 2 <= n; i += 2) {
            int d0 = __shfl_sync(0xffffffffu, myd, i);
            int d1 = __shfl_sync(0xffffffffu, myd, i + 1);
            float2 v0 = __half22float2(t2h[(size_t)d0 * 32 + lane]);
            float2 v1 = __half22float2(t2h[(size_t)d1 * 32 + lane]);
            ax += v0.x + v1.x; ay += v0.y + v1.y;
        }
        for (; i < n; i++) {
            int d = __shfl_sync(0xffffffffu, myd, i);
            float2 v = __half22float2(t2h[(size_t)d * 32 + lane]);
            ax += v.x; ay += v.y;
        }
    }
    int deg = end - beg;
    float inv = deg > 0 ? 1.f / (float)deg : 0.f;
    ((float2*)(out + (size_t)gw * D_OUT))[lane] = make_float2(ax * inv, ay * inv);
}

// ---------------- launch ----------------------------------------------------
extern "C" void kernel_launch(void* const* d_in, const int* in_sizes, int n_in,
                              void* d_out, int out_size) {
    const float* X  = (const float*)d_in[0];
    const int*   ei = (const int*)d_in[1];
    const float* W1 = (const float*)d_in[2];
    const float* W2 = (const float*)d_in[3];
    float* out = (float*)d_out;

    void* p;
    cudaGetSymbolAddress(&p, g_t1h); __half* t1 = (__half*)p;
    cudaGetSymbolAddress(&p, g_t2h); __half* t2 = (__half*)p;
    cudaGetSymbolAddress(&p, g_X16); __half* X16 = (__half*)p;
    cudaGetSymbolAddress(&p, g_H16); __half* H16 = (__half*)p;
    cudaGetSymbolAddress(&p, g_B1);  __half* B1 = (__half*)p;
    cudaGetSymbolAddress(&p, g_B2);  __half* B2 = (__half*)p;

    const int SMEM = 2 * (128 + 64) * RS * 2;   // 55296
    static cudaStream_t s2 = nullptr;
    static cudaEvent_t evF = nullptr, evJ = nullptr;
    if (s2 == nullptr) {
        cudaFuncSetAttribute((const void*)gemm_mma_kernel<128, 64, 4, 2, __half>,
                             cudaFuncAttributeMaxDynamicSharedMemorySize, SMEM);
        cudaStreamCreateWithFlags(&s2, cudaStreamNonBlocking);
        cudaEventCreateWithFlags(&evF, cudaEventDisableTiming);
        cudaEventCreateWithFlags(&evJ, cudaEventDisableTiming);
    }

    // ---- fork: CSR chain on s2, dense chain on origin stream ----
    cudaEventRecord(evF, 0);
    cudaStreamWaitEvent(s2, evF, 0);

    // CSR build (stream s2)
    zero_counts_kernel<<<(N_NODES + 255) / 256, 256, 0, s2>>>();
    hist_kernel<<<(N_EDGES / 4 + 255) / 256, 256, 0, s2>>>(ei);
    scan1_kernel<<<SCAN_NB, 1024, 0, s2>>>();
    scan2_kernel<<<1, 64, 0, s2>>>();
    scan3_kernel<<<SCAN_NB, 1024, 0, s2>>>();
    scatter_kernel<<<(N_EDGES / 4 + 255) / 256, 256, 0, s2>>>(ei);
    cudaEventRecord(evJ, s2);

    // dense chain (origin stream)
    conv_x_kernel<<<(N_NODES * D_IN / 4 + 255) / 256, 256>>>(X);
    pack_b1_kernel<<<(H1 * D_IN + 255) / 256, 256>>>(W1);
    pack_b2_kernel<<<(D_OUT * H1 + 255) / 256, 256>>>(W2);
    {
        dim3 grid(H1 / 64, (N_NODES + 127) / 128);
        gemm_mma_kernel<128, 64, 4, 2, __half><<<grid, 256, SMEM>>>(
            X16, B1, t1, N_NODES, H1, D_IN);
    }

    // ---- join ----
    cudaStreamWaitEvent(0, evJ, 0);

    agg1_kernel<<<N_NODES, 128>>>();
    {
        dim3 grid(1, (N_NODES + 127) / 128);
        gemm_mma_kernel<128, 64, 4, 2, __half><<<grid, 256, SMEM>>>(
            H16, B2, t2, N_NODES, D_OUT, H1);
    }
    agg2_kernel<<<(N_NODES * 32 + 255) / 256, 256>>>(out);
}